// round 2
// baseline (speedup 1.0000x reference)
#include <cuda_runtime.h>
#include <cuda_bf16.h>
#include <math.h>

// ---------------- problem constants ----------------
#define BB 2
#define DIMC 256
#define GG 4
#define CHG 64          // DIM/GROUPS
#define OFFD 128
#define NBG 8           // B*GROUPS
#define FF 4
#define HH 16
#define WW 16
#define PQ 1024         // F*H*W
#define FD 2
#define HD 8
#define WD 8
#define PJ 128          // FD*HD*WD
#define NHEADS 8
#define DH 64
#define CPB 64
#define INNER 512
#define IT 8            // queries per block in kernel D
#define KP 66           // padded K stride for bf16 smem tiles (bank-conflict-free)

// ---------------- scratch (static device memory; no allocs allowed) -------
__device__ float g_q[NBG * OFFD * PQ];        // (bg, 128, 1024)  4 MB
__device__ float g_grid[NBG * PJ * 3];        // normalized kv coords
__device__ float g_k[NBG * OFFD * PJ];        // (bg, 128, 128)
__device__ float g_v[NBG * OFFD * PJ];
__device__ float g_att[BB * INNER * PQ];      // (b, 512, 1024)   2 MB

// ---------------- packed f32x2 helpers ----------------
__device__ __forceinline__ unsigned long long ffma2(unsigned long long a,
                                                    unsigned long long b,
                                                    unsigned long long c) {
    unsigned long long d;
    asm("fma.rn.f32x2 %0, %1, %2, %3;" : "=l"(d) : "l"(a), "l"(b), "l"(c));
    return d;
}
__device__ __forceinline__ float2 unpack2(unsigned long long v) {
    float2 r;
    asm("mov.b64 {%0, %1}, %2;" : "=f"(r.x), "=f"(r.y) : "l"(v));
    return r;
}

// bf16 mma m16n8k16: D = A*B + C (fp32 accum)
__device__ __forceinline__ void mma16816(float* c, const unsigned* a, const unsigned* b) {
    asm volatile(
        "mma.sync.aligned.m16n8k16.row.col.f32.bf16.bf16.f32 "
        "{%0,%1,%2,%3}, {%4,%5,%6,%7}, {%8,%9}, {%0,%1,%2,%3};"
        : "+f"(c[0]), "+f"(c[1]), "+f"(c[2]), "+f"(c[3])
        : "r"(a[0]), "r"(a[1]), "r"(a[2]), "r"(a[3]), "r"(b[0]), "r"(b[1]));
}

// ============================================================
// Kernel A: grouped 1x1 conv -> q   (bg,128,1024)
// ============================================================
__global__ void k_qproj(const float* __restrict__ x, const float* __restrict__ wq) {
    const int bg = blockIdx.y;              // 0..7
    const int b = bg >> 2, g = bg & 3;
    const int p0 = blockIdx.x * 16;
    const int o = threadIdx.x;              // 0..127

    __shared__ float xs[CHG * 16];
    for (int e = threadIdx.x; e < CHG * 16; e += 128) {
        int i = e >> 4, p = e & 15;
        xs[e] = x[(size_t)(b * DIMC + g * CHG + i) * PQ + p0 + p];
    }
    __syncthreads();

    float wr[CHG];
#pragma unroll
    for (int i = 0; i < CHG; i++) wr[i] = wq[(g * OFFD + o) * CHG + i];

    for (int p = 0; p < 16; p++) {
        float acc = 0.f;
#pragma unroll
        for (int i = 0; i < CHG; i++) acc = fmaf(wr[i], xs[i * 16 + p], acc);
        g_q[(size_t)(bg * OFFD + o) * PQ + p0 + p] = acc;
    }
}

// ============================================================
// Kernel B: depthwise 4^3 stride-2 conv + GELU + 1x1 + tanh -> grid coords
// ============================================================
__global__ void k_offsets(const float* __restrict__ dww, const float* __restrict__ dwb,
                          const float* __restrict__ pww) {
    const int pos = blockIdx.x;     // 0..127
    const int bg = blockIdx.y;
    const int c = threadIdx.x;
    const int lane = c & 31, wid = c >> 5;

    const int zo = pos >> 6;
    const int yo = (pos >> 3) & 7;
    const int xo = pos & 7;

    const float* qrow = g_q + (size_t)(bg * OFFD + c) * PQ;
    float acc = 0.f;
#pragma unroll
    for (int kz = 0; kz < 4; kz++) {
        int z = 2 * zo - 1 + kz;
        if (z < 0 || z >= FF) continue;
#pragma unroll
        for (int ky = 0; ky < 4; ky++) {
            int y = 2 * yo - 1 + ky;
            if (y < 0 || y >= HH) continue;
#pragma unroll
            for (int kx = 0; kx < 4; kx++) {
                int xx = 2 * xo - 1 + kx;
                if (xx < 0 || xx >= WW) continue;
                acc = fmaf(qrow[(z * HH + y) * WW + xx],
                           dww[c * 64 + (kz * 4 + ky) * 4 + kx], acc);
            }
        }
    }
    float v = acc + dwb[c];
    float act = 0.5f * v * (1.f + erff(v * 0.70710678118654752f));

    __shared__ float acts[OFFD];
    __shared__ float sred[3];
    acts[c] = act;
    __syncthreads();

    if (wid < 3) {
        float s = 0.f;
#pragma unroll
        for (int q = 0; q < 4; q++) {
            int cc = lane + q * 32;
            s = fmaf(acts[cc], pww[wid * OFFD + cc], s);
        }
#pragma unroll
        for (int off = 16; off; off >>= 1) s += __shfl_xor_sync(0xffffffffu, s, off);
        if (lane == 0) sred[wid] = s;
    }
    __syncthreads();

    if (c == 0) {
        float of = tanhf(sred[0]) * 2.0f;
        float oh = tanhf(sred[1]) * 2.0f;
        float ow = tanhf(sred[2]) * 2.0f;
        float vf = (float)zo + of;
        float vh = (float)yo + oh;
        float vw = (float)xo + ow;
        float gf = 2.0f * vf / 1.0f - 1.0f;
        float gh = 2.0f * vh / 7.0f - 1.0f;
        float gw = 2.0f * vw / 7.0f - 1.0f;
        float* gp = g_grid + (size_t)(bg * PJ + pos) * 3;
        gp[0] = gf; gp[1] = gh; gp[2] = gw;
    }
}

// ============================================================
// Kernel C: trilinear grid-sample + k/v projections
// ============================================================
__global__ void k_sample_kv(const float* __restrict__ x, const float* __restrict__ wk,
                            const float* __restrict__ wv) {
    const int j = blockIdx.x;
    const int bg = blockIdx.y;
    const int b = bg >> 2, g = bg & 3;
    const int tid = threadIdx.x;

    const float* gp = g_grid + (size_t)(bg * PJ + j) * 3;
    const float g0 = gp[0], g1 = gp[1], g2 = gp[2];

    __shared__ float kvs[CHG];

    if (tid < CHG) {
        float ix = ((g0 + 1.f) * (float)WW - 1.f) * 0.5f;
        float iy = ((g1 + 1.f) * (float)HH - 1.f) * 0.5f;
        float iz = ((g2 + 1.f) * (float)FF - 1.f) * 0.5f;
        float fx0 = floorf(ix), fy0 = floorf(iy), fz0 = floorf(iz);
        float tx = ix - fx0, ty = iy - fy0, tz = iz - fz0;
        int x0 = (int)fx0, y0 = (int)fy0, z0 = (int)fz0;

        const float* xp = x + (size_t)(b * DIMC + g * CHG + tid) * PQ;
        float acc = 0.f;
#pragma unroll
        for (int dz = 0; dz < 2; dz++)
#pragma unroll
            for (int dy = 0; dy < 2; dy++)
#pragma unroll
                for (int dx = 0; dx < 2; dx++) {
                    int xc = x0 + dx, yc = y0 + dy, zc = z0 + dz;
                    float wgt = (dx ? tx : 1.f - tx) * (dy ? ty : 1.f - ty) *
                                (dz ? tz : 1.f - tz);
                    bool valid = (xc >= 0) & (xc < WW) & (yc >= 0) & (yc < HH) &
                                 (zc >= 0) & (zc < FF);
                    int xi = min(max(xc, 0), WW - 1);
                    int yi = min(max(yc, 0), HH - 1);
                    int zi = min(max(zc, 0), FF - 1);
                    float val = xp[(zi * HH + yi) * WW + xi];
                    acc += valid ? val * wgt : 0.f;
                }
        kvs[tid] = acc;
    }
    __syncthreads();

    float ak = 0.f, av = 0.f;
#pragma unroll
    for (int i = 0; i < CHG; i++) {
        float kv = kvs[i];
        ak = fmaf(wk[(g * OFFD + tid) * CHG + i], kv, ak);
        av = fmaf(wv[(g * OFFD + tid) * CHG + i], kv, av);
    }
    g_k[(size_t)(bg * OFFD + tid) * PJ + j] = ak;
    g_v[(size_t)(bg * OFFD + tid) * PJ + j] = av;
}

// ============================================================
// Kernel D v2: fused sim + CPB MLP (tensor-core 64x64) + softmax + attn@V
// block = (i-tile of 8, bg); 128 threads (4 warps); M-dim of MMA = j (128)
// 64x64 layer via mma.sync bf16 with 3-term hi/lo split (fp32-accurate)
// ============================================================
struct __align__(16) SmemD {
    __nv_bfloat16 w1h[CPB * KP];   // [n][k] transposed, hi part
    __nv_bfloat16 w1l[CPB * KP];   // lo part
    __nv_bfloat16 h0h[PJ * KP];    // [j][k] hi
    __nv_bfloat16 h0l[PJ * KP];    // [j][k] lo
    float qs[OFFD * IT];           // scaled q
    float attns[IT * 2 * PJ];
    float biasS[PJ * 2];
    float w0s[3 * CPB], b0s[CPB], b1s[CPB];
    float w2s0[CPB], w2s1[CPB], b2s[2];
    float red[8];
};

__global__ __launch_bounds__(128, 2)
void k_attn(const float* __restrict__ cw0, const float* __restrict__ cb0,
            const float* __restrict__ cw1, const float* __restrict__ cb1,
            const float* __restrict__ cw2, const float* __restrict__ cb2) {
    extern __shared__ SmemD sm[];
    SmemD& s = sm[0];

    const int bg = blockIdx.y;
    const int b = bg >> 2, g = bg & 3;
    const int i0 = blockIdx.x * IT;
    const int j = threadIdx.x;
    const int lane = j & 31, w = j >> 5;

    // ---- stage weights ----
    for (int e = j; e < CPB * CPB; e += 128) {
        int k = e >> 6, n = e & 63;
        float wv = cw1[e];
        __nv_bfloat16 hi = __float2bfloat16_rn(wv);
        __nv_bfloat16 lo = __float2bfloat16_rn(wv - __bfloat162float(hi));
        s.w1h[n * KP + k] = hi;
        s.w1l[n * KP + k] = lo;
    }
    for (int e = j; e < 3 * CPB; e += 128) s.w0s[e] = cw0[e];
    if (j < CPB) {
        s.b0s[j] = cb0[j];
        s.b1s[j] = cb1[j];
        s.w2s0[j] = cw2[j * 2 + 0];
        s.w2s1[j] = cw2[j * 2 + 1];
    }
    if (j < 2) s.b2s[j] = cb2[j];
    {
        const float* qp = g_q + (size_t)(bg * OFFD + j) * PQ + i0;
#pragma unroll
        for (int t = 0; t < IT; t++) s.qs[j * IT + t] = qp[t] * 0.125f;  // scale
    }
    const float* gp = g_grid + (size_t)(bg * PJ + j) * 3;
    const float gj0 = gp[0], gj1 = gp[1], gj2 = gp[2];
    __syncthreads();

    // ---- sim for the 8 queries, two head halves (thread = key j) ----
    float sim0[IT], sim1[IT];
#pragma unroll
    for (int t = 0; t < IT; t++) { sim0[t] = 0.f; sim1[t] = 0.f; }
    const float* kb = g_k + (size_t)bg * OFFD * PJ + j;
#pragma unroll 4
    for (int o = 0; o < 64; o++) {
        float kv = kb[o * PJ];
        float4 qa = *(const float4*)(s.qs + o * IT);
        float4 qbv = *(const float4*)(s.qs + o * IT + 4);
        sim0[0] = fmaf(qa.x, kv, sim0[0]); sim0[1] = fmaf(qa.y, kv, sim0[1]);
        sim0[2] = fmaf(qa.z, kv, sim0[2]); sim0[3] = fmaf(qa.w, kv, sim0[3]);
        sim0[4] = fmaf(qbv.x, kv, sim0[4]); sim0[5] = fmaf(qbv.y, kv, sim0[5]);
        sim0[6] = fmaf(qbv.z, kv, sim0[6]); sim0[7] = fmaf(qbv.w, kv, sim0[7]);
    }
#pragma unroll 4
    for (int o = 64; o < 128; o++) {
        float kv = kb[o * PJ];
        float4 qa = *(const float4*)(s.qs + o * IT);
        float4 qbv = *(const float4*)(s.qs + o * IT + 4);
        sim1[0] = fmaf(qa.x, kv, sim1[0]); sim1[1] = fmaf(qa.y, kv, sim1[1]);
        sim1[2] = fmaf(qa.z, kv, sim1[2]); sim1[3] = fmaf(qa.w, kv, sim1[3]);
        sim1[4] = fmaf(qbv.x, kv, sim1[4]); sim1[5] = fmaf(qbv.y, kv, sim1[5]);
        sim1[6] = fmaf(qbv.z, kv, sim1[6]); sim1[7] = fmaf(qbv.w, kv, sim1[7]);
    }

    // ---- per query: h0 features -> tensor MMA -> bias -> softmax ----
    for (int t = 0; t < IT; t++) {
        const int i = i0 + t;
        const int zf = i >> 8, yq = (i >> 4) & 15, xq = i & 15;
        const float gq0 = 2.0f * (float)zf / 3.0f - 1.0f;
        const float gq1 = 2.0f * (float)yq / 15.0f - 1.0f;
        const float gq2 = 2.0f * (float)xq / 15.0f - 1.0f;
        float p0 = gq0 - gj0, p1 = gq1 - gj1, p2 = gq2 - gj2;
        float t0 = copysignf(log1pf(fabsf(p0)), p0);
        float t1 = copysignf(log1pf(fabsf(p1)), p1);
        float t2 = copysignf(log1pf(fabsf(p2)), p2);

        // layer0: 3 -> 64 (thread j computes its own row), split to bf16 hi/lo
#pragma unroll
        for (int k2 = 0; k2 < CPB; k2 += 2) {
            float va = fmaf(t0, s.w0s[k2],
                       fmaf(t1, s.w0s[64 + k2],
                       fmaf(t2, s.w0s[128 + k2], s.b0s[k2])));
            float vb = fmaf(t0, s.w0s[k2 + 1],
                       fmaf(t1, s.w0s[64 + k2 + 1],
                       fmaf(t2, s.w0s[128 + k2 + 1], s.b0s[k2 + 1])));
            va = fmaxf(va, 0.f);
            vb = fmaxf(vb, 0.f);
            __nv_bfloat16 ha = __float2bfloat16_rn(va);
            __nv_bfloat16 hb = __float2bfloat16_rn(vb);
            __nv_bfloat16 la = __float2bfloat16_rn(va - __bfloat162float(ha));
            __nv_bfloat16 lb = __float2bfloat16_rn(vb - __bfloat162float(hb));
            *(__nv_bfloat162*)&s.h0h[j * KP + k2] = __nv_bfloat162(ha, hb);
            *(__nv_bfloat162*)&s.h0l[j * KP + k2] = __nv_bfloat162(la, lb);
        }
        __syncthreads();

        // ---- MMA: warp w computes h1 rows [w*32, w*32+32) x 64 cols ----
        float acc[2][8][4];
#pragma unroll
        for (int mt = 0; mt < 2; mt++)
#pragma unroll
            for (int nf = 0; nf < 8; nf++)
#pragma unroll
                for (int q = 0; q < 4; q++) acc[mt][nf][q] = 0.f;

#pragma unroll
        for (int kt = 0; kt < 4; kt++) {
            unsigned ah[2][4], al[2][4];
#pragma unroll
            for (int mt = 0; mt < 2; mt++) {
                int r0 = w * 32 + mt * 16 + (lane >> 2);
                int c0 = kt * 16 + (lane & 3) * 2;
                ah[mt][0] = *(const unsigned*)&s.h0h[r0 * KP + c0];
                ah[mt][1] = *(const unsigned*)&s.h0h[(r0 + 8) * KP + c0];
                ah[mt][2] = *(const unsigned*)&s.h0h[r0 * KP + c0 + 8];
                ah[mt][3] = *(const unsigned*)&s.h0h[(r0 + 8) * KP + c0 + 8];
                al[mt][0] = *(const unsigned*)&s.h0l[r0 * KP + c0];
                al[mt][1] = *(const unsigned*)&s.h0l[(r0 + 8) * KP + c0];
                al[mt][2] = *(const unsigned*)&s.h0l[r0 * KP + c0 + 8];
                al[mt][3] = *(const unsigned*)&s.h0l[(r0 + 8) * KP + c0 + 8];
            }
#pragma unroll
            for (int nf = 0; nf < 8; nf++) {
                int n = nf * 8 + (lane >> 2);
                int k = kt * 16 + (lane & 3) * 2;
                unsigned bh[2], bl[2];
                bh[0] = *(const unsigned*)&s.w1h[n * KP + k];
                bh[1] = *(const unsigned*)&s.w1h[n * KP + k + 8];
                bl[0] = *(const unsigned*)&s.w1l[n * KP + k];
                bl[1] = *(const unsigned*)&s.w1l[n * KP + k + 8];
#pragma unroll
                for (int mt = 0; mt < 2; mt++) {
                    mma16816(acc[mt][nf], ah[mt], bh);
                    mma16816(acc[mt][nf], ah[mt], bl);
                    mma16816(acc[mt][nf], al[mt], bh);
                }
            }
        }

        // ---- epilogue: relu(h1+b1) @ w2 -> per-row (out0,out1) ----
        float outp[2][2][2];  // [mt][rowhalf][head]
#pragma unroll
        for (int mt = 0; mt < 2; mt++)
#pragma unroll
            for (int rh = 0; rh < 2; rh++) {
                outp[mt][rh][0] = 0.f; outp[mt][rh][1] = 0.f;
            }
#pragma unroll
        for (int nf = 0; nf < 8; nf++) {
            int n0 = nf * 8 + (lane & 3) * 2;
            float b1a = s.b1s[n0], b1b = s.b1s[n0 + 1];
            float w2a0 = s.w2s0[n0], w2b0 = s.w2s0[n0 + 1];
            float w2a1 = s.w2s1[n0], w2b1 = s.w2s1[n0 + 1];
#pragma unroll
            for (int mt = 0; mt < 2; mt++) {
                float ha = fmaxf(acc[mt][nf][0] + b1a, 0.f);
                float hb = fmaxf(acc[mt][nf][1] + b1b, 0.f);
                outp[mt][0][0] = fmaf(ha, w2a0, fmaf(hb, w2b0, outp[mt][0][0]));
                outp[mt][0][1] = fmaf(ha, w2a1, fmaf(hb, w2b1, outp[mt][0][1]));
                float hc = fmaxf(acc[mt][nf][2] + b1a, 0.f);
                float hd = fmaxf(acc[mt][nf][3] + b1b, 0.f);
                outp[mt][1][0] = fmaf(hc, w2a0, fmaf(hd, w2b0, outp[mt][1][0]));
                outp[mt][1][1] = fmaf(hc, w2a1, fmaf(hd, w2b1, outp[mt][1][1]));
            }
        }
        // quad reduction (threads sharing a row differ in lane bits 0..1)
#pragma unroll
        for (int mt = 0; mt < 2; mt++)
#pragma unroll
            for (int rh = 0; rh < 2; rh++)
#pragma unroll
                for (int hh = 0; hh < 2; hh++) {
                    float vv = outp[mt][rh][hh];
                    vv += __shfl_xor_sync(0xffffffffu, vv, 1);
                    vv += __shfl_xor_sync(0xffffffffu, vv, 2);
                    outp[mt][rh][hh] = vv;
                }
        if ((lane & 3) == 0) {
#pragma unroll
            for (int mt = 0; mt < 2; mt++)
#pragma unroll
                for (int rh = 0; rh < 2; rh++) {
                    int jr = w * 32 + mt * 16 + (lane >> 2) + rh * 8;
                    s.biasS[jr * 2 + 0] = outp[mt][rh][0];
                    s.biasS[jr * 2 + 1] = outp[mt][rh][1];
                }
        }
        __syncthreads();

        float l0 = sim0[t] + s.biasS[j * 2 + 0] + s.b2s[0];
        float l1 = sim1[t] + s.biasS[j * 2 + 1] + s.b2s[1];

        // block softmax over 128 j (both heads)
        float m0 = l0, m1 = l1;
#pragma unroll
        for (int off = 16; off; off >>= 1) {
            m0 = fmaxf(m0, __shfl_xor_sync(0xffffffffu, m0, off));
            m1 = fmaxf(m1, __shfl_xor_sync(0xffffffffu, m1, off));
        }
        if (lane == 0) { s.red[w] = m0; s.red[4 + w] = m1; }
        __syncthreads();
        m0 = fmaxf(fmaxf(s.red[0], s.red[1]), fmaxf(s.red[2], s.red[3]));
        m1 = fmaxf(fmaxf(s.red[4], s.red[5]), fmaxf(s.red[6], s.red[7]));
        __syncthreads();
        float e0 = __expf(l0 - m0), e1 = __expf(l1 - m1);
        float s0 = e0, s1 = e1;
#pragma unroll
        for (int off = 16; off; off >>= 1) {
            s0 += __shfl_xor_sync(0xffffffffu, s0, off);
            s1 += __shfl_xor_sync(0xffffffffu, s1, off);
        }
        if (lane == 0) { s.red[w] = s0; s.red[4 + w] = s1; }
        __syncthreads();
        s0 = s.red[0] + s.red[1] + s.red[2] + s.red[3];
        s1 = s.red[4] + s.red[5] + s.red[6] + s.red[7];
        __syncthreads();
        s.attns[t * 2 * PJ + j] = e0 / s0;
        s.attns[t * 2 * PJ + PJ + j] = e1 / s1;
        __syncthreads();
    }

    // ---- attn @ V : thread = output channel o ----
    const int o = j, e = o >> 6;
    const ulonglong2* vrow = (const ulonglong2*)(g_v + (size_t)(bg * OFFD + o) * PJ);
    for (int t = 0; t < IT; t++) {
        const ulonglong2* arow = (const ulonglong2*)(s.attns + t * 2 * PJ + e * PJ);
        unsigned long long accA = 0ull, accB = 0ull;
#pragma unroll
        for (int q = 0; q < 32; q++) {
            ulonglong2 av = arow[q];
            ulonglong2 vv = vrow[q];
            accA = ffma2(av.x, vv.x, accA);
            accB = ffma2(av.y, vv.y, accB);
        }
        float2 fa = unpack2(accA), fb = unpack2(accB);
        g_att[(size_t)(b * INNER + g * OFFD + o) * PQ + i0 + t] =
            fa.x + fa.y + fb.x + fb.y;
    }
}

// ============================================================
// Kernel E: output projection
// ============================================================
__global__ void k_oproj(const float* __restrict__ wo, const float* __restrict__ bo,
                        float* __restrict__ out) {
    const int p0 = blockIdx.x * 64;
    const int o0 = blockIdx.y * 64;
    const int b = blockIdx.z;
    const int tid = threadIdx.x;        // 256
    const int tx = tid & 15, ty = tid >> 4;

    __shared__ __align__(16) float As[16 * 64];   // [k][m]
    __shared__ __align__(16) float Bs[16 * 64];   // [k][n]

    float acc[4][4];
#pragma unroll
    for (int a = 0; a < 4; a++)
#pragma unroll
        for (int c = 0; c < 4; c++) acc[a][c] = 0.f;

    for (int k0 = 0; k0 < INNER; k0 += 16) {
        {
            int m = tid >> 2, kq = (tid & 3) * 4;
            float4 wv = *(const float4*)(wo + (size_t)(o0 + m) * INNER + k0 + kq);
            As[(kq + 0) * 64 + m] = wv.x;
            As[(kq + 1) * 64 + m] = wv.y;
            As[(kq + 2) * 64 + m] = wv.z;
            As[(kq + 3) * 64 + m] = wv.w;
            int k = tid >> 4, pq = (tid & 15) * 4;
            float4 bv = *(const float4*)(g_att + (size_t)(b * INNER + k0 + k) * PQ + p0 + pq);
            *(float4*)(Bs + k * 64 + pq) = bv;
        }
        __syncthreads();
#pragma unroll
        for (int k = 0; k < 16; k++) {
            float4 am = *(const float4*)(As + k * 64 + ty * 4);
            float4 bn = *(const float4*)(Bs + k * 64 + tx * 4);
            float a4[4] = {am.x, am.y, am.z, am.w};
            float b4[4] = {bn.x, bn.y, bn.z, bn.w};
#pragma unroll
            for (int a = 0; a < 4; a++)
#pragma unroll
                for (int c = 0; c < 4; c++) acc[a][c] = fmaf(a4[a], b4[c], acc[a][c]);
        }
        __syncthreads();
    }
#pragma unroll
    for (int a = 0; a < 4; a++) {
        float bias = bo[o0 + ty * 4 + a];
#pragma unroll
        for (int c = 0; c < 4; c++)
            out[(size_t)(b * DIMC + o0 + ty * 4 + a) * PQ + p0 + tx * 4 + c] =
                acc[a][c] + bias;
    }
}

// ============================================================
extern "C" void kernel_launch(void* const* d_in, const int* in_sizes, int n_in,
                              void* d_out, int out_size) {
    const float* x    = (const float*)d_in[0];
    const float* wq   = (const float*)d_in[1];
    const float* wk   = (const float*)d_in[2];
    const float* wv   = (const float*)d_in[3];
    const float* dww  = (const float*)d_in[4];
    const float* dwb  = (const float*)d_in[5];
    const float* pww  = (const float*)d_in[6];
    const float* cw0  = (const float*)d_in[7];
    const float* cb0  = (const float*)d_in[8];
    const float* cw1  = (const float*)d_in[9];
    const float* cb1  = (const float*)d_in[10];
    const float* cw2  = (const float*)d_in[11];
    const float* cb2  = (const float*)d_in[12];
    const float* wo   = (const float*)d_in[13];
    const float* bo   = (const float*)d_in[14];
    float* out = (float*)d_out;

    cudaFuncSetAttribute(k_attn, cudaFuncAttributeMaxDynamicSharedMemorySize,
                         (int)sizeof(SmemD));

    k_qproj<<<dim3(PQ / 16, NBG), 128>>>(x, wq);
    k_offsets<<<dim3(PJ, NBG), 128>>>(dww, dwb, pww);
    k_sample_kv<<<dim3(PJ, NBG), 128>>>(x, wk, wv);
    k_attn<<<dim3(PQ / IT, NBG), 128, sizeof(SmemD)>>>(cw0, cb0, cw1, cb1, cw2, cb2);
    k_oproj<<<dim3(PQ / 64, DIMC / 64, BB), 256>>>(wo, bo, out);
}

// round 3
// speedup vs baseline: 1.7323x; 1.7323x over previous
#include <cuda_runtime.h>
#include <cuda_bf16.h>
#include <math.h>

// ---------------- problem constants ----------------
#define BB 2
#define DIMC 256
#define GG 4
#define CHG 64          // DIM/GROUPS
#define OFFD 128
#define NBG 8           // B*GROUPS
#define FF 4
#define HH 16
#define WW 16
#define PQ 1024         // F*H*W
#define FD 2
#define HD 8
#define WD 8
#define PJ 128          // FD*HD*WD
#define NHEADS 8
#define DH 64
#define CPB 64
#define INNER 512
#define IT 8            // queries per block in kernel D
#define KP 66           // padded K stride (halves) for w1 smem

// ---------------- scratch ----------------
__device__ float g_q[NBG * OFFD * PQ];
__device__ float g_grid[NBG * PJ * 3];
__device__ float g_k[NBG * OFFD * PJ];
__device__ float g_v[NBG * OFFD * PJ];
__device__ float g_att[BB * INNER * PQ];

// ---------------- helpers ----------------
__device__ __forceinline__ unsigned long long ffma2(unsigned long long a,
                                                    unsigned long long b,
                                                    unsigned long long c) {
    unsigned long long d;
    asm("fma.rn.f32x2 %0, %1, %2, %3;" : "=l"(d) : "l"(a), "l"(b), "l"(c));
    return d;
}
__device__ __forceinline__ float2 unpack2(unsigned long long v) {
    float2 r;
    asm("mov.b64 {%0, %1}, %2;" : "=f"(r.x), "=f"(r.y) : "l"(v));
    return r;
}
__device__ __forceinline__ void mma16816(float* c, const unsigned* a, const unsigned* b) {
    asm volatile(
        "mma.sync.aligned.m16n8k16.row.col.f32.bf16.bf16.f32 "
        "{%0,%1,%2,%3}, {%4,%5,%6,%7}, {%8,%9}, {%0,%1,%2,%3};"
        : "+f"(c[0]), "+f"(c[1]), "+f"(c[2]), "+f"(c[3])
        : "r"(a[0]), "r"(a[1]), "r"(a[2]), "r"(a[3]), "r"(b[0]), "r"(b[1]));
}
__device__ __forceinline__ unsigned pack_bf2(float a, float b) {
    __nv_bfloat162 t = __floats2bfloat162_rn(a, b);
    return *(unsigned*)&t;
}

// ============================================================
// Kernel A: grouped 1x1 conv -> q
// ============================================================
__global__ void k_qproj(const float* __restrict__ x, const float* __restrict__ wq) {
    const int bg = blockIdx.y;
    const int b = bg >> 2, g = bg & 3;
    const int p0 = blockIdx.x * 16;
    const int o = threadIdx.x;

    __shared__ float xs[CHG * 16];
    for (int e = threadIdx.x; e < CHG * 16; e += 128) {
        int i = e >> 4, p = e & 15;
        xs[e] = x[(size_t)(b * DIMC + g * CHG + i) * PQ + p0 + p];
    }
    __syncthreads();

    float wr[CHG];
#pragma unroll
    for (int i = 0; i < CHG; i++) wr[i] = wq[(g * OFFD + o) * CHG + i];

    for (int p = 0; p < 16; p++) {
        float acc = 0.f;
#pragma unroll
        for (int i = 0; i < CHG; i++) acc = fmaf(wr[i], xs[i * 16 + p], acc);
        g_q[(size_t)(bg * OFFD + o) * PQ + p0 + p] = acc;
    }
}

// ============================================================
// Kernel B: offsets -> deformed grid coords
// ============================================================
__global__ void k_offsets(const float* __restrict__ dww, const float* __restrict__ dwb,
                          const float* __restrict__ pww) {
    const int pos = blockIdx.x;
    const int bg = blockIdx.y;
    const int c = threadIdx.x;
    const int lane = c & 31, wid = c >> 5;

    const int zo = pos >> 6;
    const int yo = (pos >> 3) & 7;
    const int xo = pos & 7;

    const float* qrow = g_q + (size_t)(bg * OFFD + c) * PQ;
    float acc = 0.f;
#pragma unroll
    for (int kz = 0; kz < 4; kz++) {
        int z = 2 * zo - 1 + kz;
        if (z < 0 || z >= FF) continue;
#pragma unroll
        for (int ky = 0; ky < 4; ky++) {
            int y = 2 * yo - 1 + ky;
            if (y < 0 || y >= HH) continue;
#pragma unroll
            for (int kx = 0; kx < 4; kx++) {
                int xx = 2 * xo - 1 + kx;
                if (xx < 0 || xx >= WW) continue;
                acc = fmaf(qrow[(z * HH + y) * WW + xx],
                           dww[c * 64 + (kz * 4 + ky) * 4 + kx], acc);
            }
        }
    }
    float v = acc + dwb[c];
    float act = 0.5f * v * (1.f + erff(v * 0.70710678118654752f));

    __shared__ float acts[OFFD];
    __shared__ float sred[3];
    acts[c] = act;
    __syncthreads();

    if (wid < 3) {
        float s = 0.f;
#pragma unroll
        for (int q = 0; q < 4; q++) {
            int cc = lane + q * 32;
            s = fmaf(acts[cc], pww[wid * OFFD + cc], s);
        }
#pragma unroll
        for (int off = 16; off; off >>= 1) s += __shfl_xor_sync(0xffffffffu, s, off);
        if (lane == 0) sred[wid] = s;
    }
    __syncthreads();

    if (c == 0) {
        float of = tanhf(sred[0]) * 2.0f;
        float oh = tanhf(sred[1]) * 2.0f;
        float ow = tanhf(sred[2]) * 2.0f;
        float gf = 2.0f * ((float)zo + of) / 1.0f - 1.0f;
        float gh = 2.0f * ((float)yo + oh) / 7.0f - 1.0f;
        float gw = 2.0f * ((float)xo + ow) / 7.0f - 1.0f;
        float* gp = g_grid + (size_t)(bg * PJ + pos) * 3;
        gp[0] = gf; gp[1] = gh; gp[2] = gw;
    }
}

// ============================================================
// Kernel C: trilinear grid-sample + k/v projections
// ============================================================
__global__ void k_sample_kv(const float* __restrict__ x, const float* __restrict__ wk,
                            const float* __restrict__ wv) {
    const int j = blockIdx.x;
    const int bg = blockIdx.y;
    const int b = bg >> 2, g = bg & 3;
    const int tid = threadIdx.x;

    const float* gp = g_grid + (size_t)(bg * PJ + j) * 3;
    const float g0 = gp[0], g1 = gp[1], g2 = gp[2];

    __shared__ float kvs[CHG];

    if (tid < CHG) {
        float ix = ((g0 + 1.f) * (float)WW - 1.f) * 0.5f;
        float iy = ((g1 + 1.f) * (float)HH - 1.f) * 0.5f;
        float iz = ((g2 + 1.f) * (float)FF - 1.f) * 0.5f;
        float fx0 = floorf(ix), fy0 = floorf(iy), fz0 = floorf(iz);
        float tx = ix - fx0, ty = iy - fy0, tz = iz - fz0;
        int x0 = (int)fx0, y0 = (int)fy0, z0 = (int)fz0;

        const float* xp = x + (size_t)(b * DIMC + g * CHG + tid) * PQ;
        float acc = 0.f;
#pragma unroll
        for (int dz = 0; dz < 2; dz++)
#pragma unroll
            for (int dy = 0; dy < 2; dy++)
#pragma unroll
                for (int dx = 0; dx < 2; dx++) {
                    int xc = x0 + dx, yc = y0 + dy, zc = z0 + dz;
                    float wgt = (dx ? tx : 1.f - tx) * (dy ? ty : 1.f - ty) *
                                (dz ? tz : 1.f - tz);
                    bool valid = (xc >= 0) & (xc < WW) & (yc >= 0) & (yc < HH) &
                                 (zc >= 0) & (zc < FF);
                    int xi = min(max(xc, 0), WW - 1);
                    int yi = min(max(yc, 0), HH - 1);
                    int zi = min(max(zc, 0), FF - 1);
                    float val = xp[(zi * HH + yi) * WW + xi];
                    acc += valid ? val * wgt : 0.f;
                }
        kvs[tid] = acc;
    }
    __syncthreads();

    float ak = 0.f, av = 0.f;
#pragma unroll
    for (int i = 0; i < CHG; i++) {
        float kv = kvs[i];
        ak = fmaf(wk[(g * OFFD + tid) * CHG + i], kv, ak);
        av = fmaf(wv[(g * OFFD + tid) * CHG + i], kv, av);
    }
    g_k[(size_t)(bg * OFFD + tid) * PJ + j] = ak;
    g_v[(size_t)(bg * OFFD + tid) * PJ + j] = av;
}

// ============================================================
// Kernel D v3: registers-only h0 -> MMA (A split hi/lo, B=w1 bf16)
// 256 threads (8 warps); warp w owns M-rows [w*16, w*16+16)
// ============================================================
__global__ __launch_bounds__(256, 2)
void k_attn(const float* __restrict__ cw0, const float* __restrict__ cb0,
            const float* __restrict__ cw1, const float* __restrict__ cb1,
            const float* __restrict__ cw2, const float* __restrict__ cb2) {
    __shared__ __align__(16) __nv_bfloat16 w1h[CPB * KP];    // [n][k]
    __shared__ __align__(16) float ts[IT * 3 * PJ];          // [q][d][j]
    __shared__ __align__(16) float qs[OFFD * IT];            // [o][t] *scale
    __shared__ __align__(16) float attns[IT * 2 * PJ];       // [t][head][j]
    __shared__ float biasS[PJ * 2];
    __shared__ float w0s[3 * CPB], b0s[CPB], b1s[CPB], w2s0[CPB], w2s1[CPB];
    __shared__ float red[16];

    const int bg = blockIdx.y;
    const int b = bg >> 2, g = bg & 3;
    const int i0 = blockIdx.x * IT;
    const int tid = threadIdx.x;
    const int lane = tid & 31, w = tid >> 5;

    // ---- stage ----
    for (int e = tid; e < CPB * CPB; e += 256) {
        int k = e >> 6, n = e & 63;
        w1h[n * KP + k] = __float2bfloat16_rn(cw1[e]);
    }
    for (int e = tid; e < 3 * CPB; e += 256) w0s[e] = cw0[e];
    if (tid < CPB) {
        b0s[tid] = cb0[tid];
        b1s[tid] = cb1[tid];
        w2s0[tid] = cw2[tid * 2 + 0];
        w2s1[tid] = cw2[tid * 2 + 1];
    }
    {
        int o = tid >> 1, half = (tid & 1) * 4;
        float4 qv = *(const float4*)(g_q + (size_t)(bg * OFFD + o) * PQ + i0 + half);
        qs[o * IT + half + 0] = qv.x * 0.125f;
        qs[o * IT + half + 1] = qv.y * 0.125f;
        qs[o * IT + half + 2] = qv.z * 0.125f;
        qs[o * IT + half + 3] = qv.w * 0.125f;
    }
    // sign-log t table: ts[q][d][j]
    for (int e = tid; e < IT * 3 * PJ; e += 256) {
        int q = e / 384, rem = e - q * 384;
        int d = rem >> 7, j = rem & 127;
        int i = i0 + q;
        float gq;
        if (d == 0) gq = 2.0f * (float)(i >> 8) / 3.0f - 1.0f;
        else if (d == 1) gq = 2.0f * (float)((i >> 4) & 15) / 15.0f - 1.0f;
        else gq = 2.0f * (float)(i & 15) / 15.0f - 1.0f;
        float gj = g_grid[(size_t)(bg * PJ + j) * 3 + d];
        float p = gq - gj;
        ts[e] = copysignf(log1pf(fabsf(p)), p);
    }
    __syncthreads();

    // ---- sim: thread = (j = tid&127, head = tid>>7) ----
    const int jj = tid & 127, eh = tid >> 7;
    float sim[IT];
#pragma unroll
    for (int t = 0; t < IT; t++) sim[t] = 0.f;
    {
        const float* kb = g_k + (size_t)bg * OFFD * PJ + (size_t)eh * 64 * PJ + jj;
#pragma unroll 4
        for (int o = 0; o < 64; o++) {
            float kv = kb[o * PJ];
            float4 qa = *(const float4*)(qs + (eh * 64 + o) * IT);
            float4 qb = *(const float4*)(qs + (eh * 64 + o) * IT + 4);
            sim[0] = fmaf(qa.x, kv, sim[0]); sim[1] = fmaf(qa.y, kv, sim[1]);
            sim[2] = fmaf(qa.z, kv, sim[2]); sim[3] = fmaf(qa.w, kv, sim[3]);
            sim[4] = fmaf(qb.x, kv, sim[4]); sim[5] = fmaf(qb.y, kv, sim[5]);
            sim[6] = fmaf(qb.z, kv, sim[6]); sim[7] = fmaf(qb.w, kv, sim[7]);
        }
    }

    // ---- per-query: register h0 -> MMA -> epilogue -> softmax ----
    const int r = w * 16 + (lane >> 2);      // MMA row of this thread (and r+8)
    const int kq = (lane & 3) * 2;           // base k col

    for (int t = 0; t < IT; t++) {
        const float* tq = ts + t * 3 * PJ;
        float t00 = tq[r],        t01 = tq[PJ + r],        t02 = tq[2 * PJ + r];
        float t10 = tq[r + 8],    t11 = tq[PJ + r + 8],    t12 = tq[2 * PJ + r + 8];

        unsigned ah[16], al[16];
#pragma unroll
        for (int kt = 0; kt < 4; kt++) {
#pragma unroll
            for (int cp = 0; cp < 2; cp++) {          // col pair: +0 or +8
                int c0 = kt * 16 + kq + cp * 8;
                float wa0 = w0s[c0],       wa1 = w0s[64 + c0],       wa2 = w0s[128 + c0],       ba = b0s[c0];
                float wb0 = w0s[c0 + 1],   wb1 = w0s[64 + c0 + 1],   wb2 = w0s[128 + c0 + 1],   bb = b0s[c0 + 1];
                // row r
                float va = fmaxf(fmaf(t00, wa0, fmaf(t01, wa1, fmaf(t02, wa2, ba))), 0.f);
                float vb = fmaxf(fmaf(t00, wb0, fmaf(t01, wb1, fmaf(t02, wb2, bb))), 0.f);
                __nv_bfloat16 hA = __float2bfloat16_rn(va);
                __nv_bfloat16 hB = __float2bfloat16_rn(vb);
                ah[kt * 4 + cp * 2] = pack_bf2(__bfloat162float(hA), __bfloat162float(hB)) ;
                al[kt * 4 + cp * 2] = pack_bf2(va - __bfloat162float(hA), vb - __bfloat162float(hB));
                // row r+8
                float vc = fmaxf(fmaf(t10, wa0, fmaf(t11, wa1, fmaf(t12, wa2, ba))), 0.f);
                float vd = fmaxf(fmaf(t10, wb0, fmaf(t11, wb1, fmaf(t12, wb2, bb))), 0.f);
                __nv_bfloat16 hC = __float2bfloat16_rn(vc);
                __nv_bfloat16 hD = __float2bfloat16_rn(vd);
                ah[kt * 4 + cp * 2 + 1] = pack_bf2(__bfloat162float(hC), __bfloat162float(hD));
                al[kt * 4 + cp * 2 + 1] = pack_bf2(vc - __bfloat162float(hC), vd - __bfloat162float(hD));
            }
        }

        // MMA + epilogue per nf
        float outp00 = 0.f, outp01 = 0.f, outp10 = 0.f, outp11 = 0.f; // [rowhalf][head]
#pragma unroll
        for (int nf = 0; nf < 8; nf++) {
            float acc[4] = {0.f, 0.f, 0.f, 0.f};
            int nrow = nf * 8 + (lane >> 2);
#pragma unroll
            for (int kt = 0; kt < 4; kt++) {
                unsigned bb2[2];
                bb2[0] = *(const unsigned*)&w1h[nrow * KP + kt * 16 + kq];
                bb2[1] = *(const unsigned*)&w1h[nrow * KP + kt * 16 + kq + 8];
                mma16816(acc, &ah[kt * 4], bb2);
                mma16816(acc, &al[kt * 4], bb2);
            }
            int n0 = nf * 8 + kq;
            float b1a = b1s[n0], b1b = b1s[n0 + 1];
            float wa0 = w2s0[n0], wb0 = w2s0[n0 + 1];
            float wa1 = w2s1[n0], wb1 = w2s1[n0 + 1];
            float ha = fmaxf(acc[0] + b1a, 0.f);
            float hb = fmaxf(acc[1] + b1b, 0.f);
            outp00 = fmaf(ha, wa0, fmaf(hb, wb0, outp00));
            outp01 = fmaf(ha, wa1, fmaf(hb, wb1, outp01));
            float hc = fmaxf(acc[2] + b1a, 0.f);
            float hd = fmaxf(acc[3] + b1b, 0.f);
            outp10 = fmaf(hc, wa0, fmaf(hd, wb0, outp10));
            outp11 = fmaf(hc, wa1, fmaf(hd, wb1, outp11));
        }
        // quad reduce over lane&3 (different n columns)
#pragma unroll
        for (int off = 1; off <= 2; off <<= 1) {
            outp00 += __shfl_xor_sync(0xffffffffu, outp00, off);
            outp01 += __shfl_xor_sync(0xffffffffu, outp01, off);
            outp10 += __shfl_xor_sync(0xffffffffu, outp10, off);
            outp11 += __shfl_xor_sync(0xffffffffu, outp11, off);
        }
        if ((lane & 3) == 0) {
            biasS[r * 2 + 0] = outp00;
            biasS[r * 2 + 1] = outp01;
            biasS[(r + 8) * 2 + 0] = outp10;
            biasS[(r + 8) * 2 + 1] = outp11;
        }
        __syncthreads();

        // softmax over j per head (b2 bias is j-constant -> cancels)
        float l = sim[t] + biasS[jj * 2 + eh];
        float m = l;
#pragma unroll
        for (int off = 16; off; off >>= 1)
            m = fmaxf(m, __shfl_xor_sync(0xffffffffu, m, off));
        if (lane == 0) red[w] = m;
        __syncthreads();
        m = fmaxf(fmaxf(red[eh * 4 + 0], red[eh * 4 + 1]),
                  fmaxf(red[eh * 4 + 2], red[eh * 4 + 3]));
        float ev = __expf(l - m);
        float sv = ev;
#pragma unroll
        for (int off = 16; off; off >>= 1)
            sv += __shfl_xor_sync(0xffffffffu, sv, off);
        if (lane == 0) red[8 + w] = sv;
        __syncthreads();
        sv = red[8 + eh * 4 + 0] + red[8 + eh * 4 + 1] +
             red[8 + eh * 4 + 2] + red[8 + eh * 4 + 3];
        attns[t * 2 * PJ + eh * PJ + jj] = ev / sv;
    }
    __syncthreads();

    // ---- attn @ V : thread = (o = tid&127, query-half = tid>>7) ----
    {
        const int o = tid & 127, qh = tid >> 7, e = o >> 6;
        const ulonglong2* vrow = (const ulonglong2*)(g_v + (size_t)(bg * OFFD + o) * PJ);
        for (int t = qh * 4; t < qh * 4 + 4; t++) {
            const ulonglong2* arow = (const ulonglong2*)(attns + t * 2 * PJ + e * PJ);
            unsigned long long accA = 0ull, accB = 0ull;
#pragma unroll
            for (int q = 0; q < 32; q++) {
                ulonglong2 av = arow[q];
                ulonglong2 vv = vrow[q];
                accA = ffma2(av.x, vv.x, accA);
                accB = ffma2(av.y, vv.y, accB);
            }
            float2 fa = unpack2(accA), fb = unpack2(accB);
            g_att[(size_t)(b * INNER + g * OFFD + o) * PQ + i0 + t] =
                fa.x + fa.y + fb.x + fb.y;
        }
    }
}

// ============================================================
// Kernel E: output projection
// ============================================================
__global__ void k_oproj(const float* __restrict__ wo, const float* __restrict__ bo,
                        float* __restrict__ out) {
    const int p0 = blockIdx.x * 64;
    const int o0 = blockIdx.y * 64;
    const int b = blockIdx.z;
    const int tid = threadIdx.x;
    const int tx = tid & 15, ty = tid >> 4;

    __shared__ __align__(16) float As[16 * 64];
    __shared__ __align__(16) float Bs[16 * 64];

    float acc[4][4];
#pragma unroll
    for (int a = 0; a < 4; a++)
#pragma unroll
        for (int c = 0; c < 4; c++) acc[a][c] = 0.f;

    for (int k0 = 0; k0 < INNER; k0 += 16) {
        {
            int m = tid >> 2, kqq = (tid & 3) * 4;
            float4 wv = *(const float4*)(wo + (size_t)(o0 + m) * INNER + k0 + kqq);
            As[(kqq + 0) * 64 + m] = wv.x;
            As[(kqq + 1) * 64 + m] = wv.y;
            As[(kqq + 2) * 64 + m] = wv.z;
            As[(kqq + 3) * 64 + m] = wv.w;
            int k = tid >> 4, pq = (tid & 15) * 4;
            float4 bv = *(const float4*)(g_att + (size_t)(b * INNER + k0 + k) * PQ + p0 + pq);
            *(float4*)(Bs + k * 64 + pq) = bv;
        }
        __syncthreads();
#pragma unroll
        for (int k = 0; k < 16; k++) {
            float4 am = *(const float4*)(As + k * 64 + ty * 4);
            float4 bn = *(const float4*)(Bs + k * 64 + tx * 4);
            float a4[4] = {am.x, am.y, am.z, am.w};
            float b4[4] = {bn.x, bn.y, bn.z, bn.w};
#pragma unroll
            for (int a = 0; a < 4; a++)
#pragma unroll
                for (int c = 0; c < 4; c++) acc[a][c] = fmaf(a4[a], b4[c], acc[a][c]);
        }
        __syncthreads();
    }
#pragma unroll
    for (int a = 0; a < 4; a++) {
        float bias = bo[o0 + ty * 4 + a];
#pragma unroll
        for (int c = 0; c < 4; c++)
            out[(size_t)(b * DIMC + o0 + ty * 4 + a) * PQ + p0 + tx * 4 + c] =
                acc[a][c] + bias;
    }
}

// ============================================================
extern "C" void kernel_launch(void* const* d_in, const int* in_sizes, int n_in,
                              void* d_out, int out_size) {
    const float* x    = (const float*)d_in[0];
    const float* wq   = (const float*)d_in[1];
    const float* wk   = (const float*)d_in[2];
    const float* wv   = (const float*)d_in[3];
    const float* dww  = (const float*)d_in[4];
    const float* dwb  = (const float*)d_in[5];
    const float* pww  = (const float*)d_in[6];
    const float* cw0  = (const float*)d_in[7];
    const float* cb0  = (const float*)d_in[8];
    const float* cw1  = (const float*)d_in[9];
    const float* cb1  = (const float*)d_in[10];
    const float* cw2  = (const float*)d_in[11];
    const float* cb2  = (const float*)d_in[12];
    const float* wo   = (const float*)d_in[13];
    const float* bo   = (const float*)d_in[14];
    float* out = (float*)d_out;

    k_qproj<<<dim3(PQ / 16, NBG), 128>>>(x, wq);
    k_offsets<<<dim3(PJ, NBG), 128>>>(dww, dwb, pww);
    k_sample_kv<<<dim3(PJ, NBG), 128>>>(x, wk, wv);
    k_attn<<<dim3(PQ / IT, NBG), 256>>>(cw0, cb0, cw1, cb1, cw2, cb2);
    k_oproj<<<dim3(PQ / 64, DIMC / 64, BB), 256>>>(wo, bo, out);
}

// round 4
// speedup vs baseline: 1.9106x; 1.1030x over previous
#include <cuda_runtime.h>
#include <cuda_bf16.h>
#include <math.h>

// ---------------- problem constants ----------------
#define BB 2
#define DIMC 256
#define GG 4
#define CHG 64          // DIM/GROUPS
#define OFFD 128
#define NBG 8           // B*GROUPS
#define FF 4
#define HH 16
#define WW 16
#define PQ 1024         // F*H*W
#define FD 2
#define HD 8
#define WD 8
#define PJ 128          // FD*HD*WD
#define NHEADS 8
#define DH 64
#define CPB 64
#define INNER 512
#define IT 8            // queries per block in kernel D
#define KP 66           // padded K stride (halves) for w1 smem

// ---------------- scratch ----------------
__device__ float g_q[NBG * OFFD * PQ];
__device__ float g_grid[NBG * PJ * 3];
__device__ float g_k[NBG * OFFD * PJ];
__device__ float g_v[NBG * OFFD * PJ];
__device__ float g_att[BB * INNER * PQ];

// ---------------- helpers ----------------
__device__ __forceinline__ unsigned long long ffma2(unsigned long long a,
                                                    unsigned long long b,
                                                    unsigned long long c) {
    unsigned long long d;
    asm("fma.rn.f32x2 %0, %1, %2, %3;" : "=l"(d) : "l"(a), "l"(b), "l"(c));
    return d;
}
__device__ __forceinline__ float2 unpack2(unsigned long long v) {
    float2 r;
    asm("mov.b64 {%0, %1}, %2;" : "=f"(r.x), "=f"(r.y) : "l"(v));
    return r;
}
__device__ __forceinline__ void mma16816(float* c, const unsigned* a, const unsigned* b) {
    asm volatile(
        "mma.sync.aligned.m16n8k16.row.col.f32.bf16.bf16.f32 "
        "{%0,%1,%2,%3}, {%4,%5,%6,%7}, {%8,%9}, {%0,%1,%2,%3};"
        : "+f"(c[0]), "+f"(c[1]), "+f"(c[2]), "+f"(c[3])
        : "r"(a[0]), "r"(a[1]), "r"(a[2]), "r"(a[3]), "r"(b[0]), "r"(b[1]));
}
__device__ __forceinline__ unsigned pack_bf2(float a, float b) {
    __nv_bfloat162 t = __floats2bfloat162_rn(a, b);
    return *(unsigned*)&t;
}

// ============================================================
// Kernel A: grouped 1x1 conv -> q
// ============================================================
__global__ void k_qproj(const float* __restrict__ x, const float* __restrict__ wq) {
    const int bg = blockIdx.y;
    const int b = bg >> 2, g = bg & 3;
    const int p0 = blockIdx.x * 16;
    const int o = threadIdx.x;

    __shared__ float xs[CHG * 16];
    for (int e = threadIdx.x; e < CHG * 16; e += 128) {
        int i = e >> 4, p = e & 15;
        xs[e] = x[(size_t)(b * DIMC + g * CHG + i) * PQ + p0 + p];
    }
    __syncthreads();

    float wr[CHG];
#pragma unroll
    for (int i = 0; i < CHG; i++) wr[i] = wq[(g * OFFD + o) * CHG + i];

    for (int p = 0; p < 16; p++) {
        float acc = 0.f;
#pragma unroll
        for (int i = 0; i < CHG; i++) acc = fmaf(wr[i], xs[i * 16 + p], acc);
        g_q[(size_t)(bg * OFFD + o) * PQ + p0 + p] = acc;
    }
}

// ============================================================
// Kernel B: offsets -> deformed grid coords
// ============================================================
__global__ void k_offsets(const float* __restrict__ dww, const float* __restrict__ dwb,
                          const float* __restrict__ pww) {
    const int pos = blockIdx.x;
    const int bg = blockIdx.y;
    const int c = threadIdx.x;
    const int lane = c & 31, wid = c >> 5;

    const int zo = pos >> 6;
    const int yo = (pos >> 3) & 7;
    const int xo = pos & 7;

    const float* qrow = g_q + (size_t)(bg * OFFD + c) * PQ;
    float acc = 0.f;
#pragma unroll
    for (int kz = 0; kz < 4; kz++) {
        int z = 2 * zo - 1 + kz;
        if (z < 0 || z >= FF) continue;
#pragma unroll
        for (int ky = 0; ky < 4; ky++) {
            int y = 2 * yo - 1 + ky;
            if (y < 0 || y >= HH) continue;
#pragma unroll
            for (int kx = 0; kx < 4; kx++) {
                int xx = 2 * xo - 1 + kx;
                if (xx < 0 || xx >= WW) continue;
                acc = fmaf(qrow[(z * HH + y) * WW + xx],
                           dww[c * 64 + (kz * 4 + ky) * 4 + kx], acc);
            }
        }
    }
    float v = acc + dwb[c];
    float act = 0.5f * v * (1.f + erff(v * 0.70710678118654752f));

    __shared__ float acts[OFFD];
    __shared__ float sred[3];
    acts[c] = act;
    __syncthreads();

    if (wid < 3) {
        float s = 0.f;
#pragma unroll
        for (int q = 0; q < 4; q++) {
            int cc = lane + q * 32;
            s = fmaf(acts[cc], pww[wid * OFFD + cc], s);
        }
#pragma unroll
        for (int off = 16; off; off >>= 1) s += __shfl_xor_sync(0xffffffffu, s, off);
        if (lane == 0) sred[wid] = s;
    }
    __syncthreads();

    if (c == 0) {
        float of = tanhf(sred[0]) * 2.0f;
        float oh = tanhf(sred[1]) * 2.0f;
        float ow = tanhf(sred[2]) * 2.0f;
        float gf = 2.0f * ((float)zo + of) / 1.0f - 1.0f;
        float gh = 2.0f * ((float)yo + oh) / 7.0f - 1.0f;
        float gw = 2.0f * ((float)xo + ow) / 7.0f - 1.0f;
        float* gp = g_grid + (size_t)(bg * PJ + pos) * 3;
        gp[0] = gf; gp[1] = gh; gp[2] = gw;
    }
}

// ============================================================
// Kernel C: trilinear grid-sample + k/v projections
// ============================================================
__global__ void k_sample_kv(const float* __restrict__ x, const float* __restrict__ wk,
                            const float* __restrict__ wv) {
    const int j = blockIdx.x;
    const int bg = blockIdx.y;
    const int b = bg >> 2, g = bg & 3;
    const int tid = threadIdx.x;

    const float* gp = g_grid + (size_t)(bg * PJ + j) * 3;
    const float g0 = gp[0], g1 = gp[1], g2 = gp[2];

    __shared__ float kvs[CHG];

    if (tid < CHG) {
        float ix = ((g0 + 1.f) * (float)WW - 1.f) * 0.5f;
        float iy = ((g1 + 1.f) * (float)HH - 1.f) * 0.5f;
        float iz = ((g2 + 1.f) * (float)FF - 1.f) * 0.5f;
        float fx0 = floorf(ix), fy0 = floorf(iy), fz0 = floorf(iz);
        float tx = ix - fx0, ty = iy - fy0, tz = iz - fz0;
        int x0 = (int)fx0, y0 = (int)fy0, z0 = (int)fz0;

        const float* xp = x + (size_t)(b * DIMC + g * CHG + tid) * PQ;
        float acc = 0.f;
#pragma unroll
        for (int dz = 0; dz < 2; dz++)
#pragma unroll
            for (int dy = 0; dy < 2; dy++)
#pragma unroll
                for (int dx = 0; dx < 2; dx++) {
                    int xc = x0 + dx, yc = y0 + dy, zc = z0 + dz;
                    float wgt = (dx ? tx : 1.f - tx) * (dy ? ty : 1.f - ty) *
                                (dz ? tz : 1.f - tz);
                    bool valid = (xc >= 0) & (xc < WW) & (yc >= 0) & (yc < HH) &
                                 (zc >= 0) & (zc < FF);
                    int xi = min(max(xc, 0), WW - 1);
                    int yi = min(max(yc, 0), HH - 1);
                    int zi = min(max(zc, 0), FF - 1);
                    float val = xp[(zi * HH + yi) * WW + xi];
                    acc += valid ? val * wgt : 0.f;
                }
        kvs[tid] = acc;
    }
    __syncthreads();

    float ak = 0.f, av = 0.f;
#pragma unroll
    for (int i = 0; i < CHG; i++) {
        float kv = kvs[i];
        ak = fmaf(wk[(g * OFFD + tid) * CHG + i], kv, ak);
        av = fmaf(wv[(g * OFFD + tid) * CHG + i], kv, av);
    }
    g_k[(size_t)(bg * OFFD + tid) * PJ + j] = ak;
    g_v[(size_t)(bg * OFFD + tid) * PJ + j] = av;
}

// ============================================================
// Kernel D v4: B-frags resident in regs, single-term bf16 MMA,
// vectorized w0/w2 tables, 2 syncs/query, no-max softmax.
// 256 threads (8 warps); warp w owns M-rows [w*16, w*16+16)
// ============================================================
__global__ __launch_bounds__(256, 2)
void k_attn(const float* __restrict__ cw0, const float* __restrict__ cb0,
            const float* __restrict__ cw1, const float* __restrict__ cb1,
            const float* __restrict__ cw2, const float* __restrict__ cb2) {
    __shared__ __align__(16) __nv_bfloat16 w1h[CPB * KP];    // [n][k]
    __shared__ __align__(16) float ts[IT * 3 * PJ];          // [q][d][j]
    __shared__ __align__(16) float qs[OFFD * IT];            // [o][t] *scale
    __shared__ __align__(16) float attns[IT * 2 * PJ];       // [t][head][j]
    __shared__ __align__(16) float4 w0i[CPB];                // {w0_0,w0_1,w0_2,b0}[c]
    __shared__ __align__(16) float4 w2i[CPB / 2];            // {w2c0h0,w2c1h0,w2c0h1,w2c1h1}
    __shared__ __align__(16) float2 b1i[CPB / 2];
    __shared__ float biasS[PJ * 2];
    __shared__ float red[16];

    const int bg = blockIdx.y;
    const int b = bg >> 2, g = bg & 3;
    const int i0 = blockIdx.x * IT;
    const int tid = threadIdx.x;
    const int lane = tid & 31, w = tid >> 5;

    // ---- stage ----
    for (int e = tid; e < CPB * CPB; e += 256) {
        int k = e >> 6, n = e & 63;
        w1h[n * KP + k] = __float2bfloat16_rn(cw1[e]);
    }
    if (tid < CPB)
        w0i[tid] = make_float4(cw0[tid], cw0[64 + tid], cw0[128 + tid], cb0[tid]);
    if (tid < CPB / 2) {
        int c = tid * 2;
        w2i[tid] = make_float4(cw2[c * 2 + 0], cw2[c * 2 + 2],
                               cw2[c * 2 + 1], cw2[c * 2 + 3]);
        b1i[tid] = make_float2(cb1[c], cb1[c + 1]);
    }
    {
        int o = tid >> 1, half = (tid & 1) * 4;
        float4 qv = *(const float4*)(g_q + (size_t)(bg * OFFD + o) * PQ + i0 + half);
        qs[o * IT + half + 0] = qv.x * 0.125f;
        qs[o * IT + half + 1] = qv.y * 0.125f;
        qs[o * IT + half + 2] = qv.z * 0.125f;
        qs[o * IT + half + 3] = qv.w * 0.125f;
    }
    // sign-log t table: ts[q][d][j]
    for (int e = tid; e < IT * 3 * PJ; e += 256) {
        int q = e / 384, rem = e - q * 384;
        int d = rem >> 7, j = rem & 127;
        int i = i0 + q;
        float gq;
        if (d == 0) gq = 2.0f * (float)(i >> 8) / 3.0f - 1.0f;
        else if (d == 1) gq = 2.0f * (float)((i >> 4) & 15) / 15.0f - 1.0f;
        else gq = 2.0f * (float)(i & 15) / 15.0f - 1.0f;
        float gj = g_grid[(size_t)(bg * PJ + j) * 3 + d];
        float p = gq - gj;
        ts[e] = copysignf(log1pf(fabsf(p)), p);
    }
    __syncthreads();

    const int r = w * 16 + (lane >> 2);      // MMA row (and r+8)
    const int kq = (lane & 3) * 2;           // base k col

    // ---- hoist w1 B-fragments into registers (query-invariant) ----
    unsigned bfr[8][4][2];
#pragma unroll
    for (int nf = 0; nf < 8; nf++) {
        int nrow = nf * 8 + (lane >> 2);
#pragma unroll
        for (int kt = 0; kt < 4; kt++) {
            bfr[nf][kt][0] = *(const unsigned*)&w1h[nrow * KP + kt * 16 + kq];
            bfr[nf][kt][1] = *(const unsigned*)&w1h[nrow * KP + kt * 16 + kq + 8];
        }
    }

    // ---- sim: thread = (j = tid&127, head = tid>>7) ----
    const int jj = tid & 127, eh = tid >> 7;
    float sim[IT];
#pragma unroll
    for (int t = 0; t < IT; t++) sim[t] = 0.f;
    {
        const float* kb = g_k + (size_t)bg * OFFD * PJ + (size_t)eh * 64 * PJ + jj;
#pragma unroll 4
        for (int o = 0; o < 64; o++) {
            float kv = kb[o * PJ];
            float4 qa = *(const float4*)(qs + (eh * 64 + o) * IT);
            float4 qb = *(const float4*)(qs + (eh * 64 + o) * IT + 4);
            sim[0] = fmaf(qa.x, kv, sim[0]); sim[1] = fmaf(qa.y, kv, sim[1]);
            sim[2] = fmaf(qa.z, kv, sim[2]); sim[3] = fmaf(qa.w, kv, sim[3]);
            sim[4] = fmaf(qb.x, kv, sim[4]); sim[5] = fmaf(qb.y, kv, sim[5]);
            sim[6] = fmaf(qb.z, kv, sim[6]); sim[7] = fmaf(qb.w, kv, sim[7]);
        }
    }

    // ---- per-query: register h0 -> MMA -> epilogue -> softmax ----
    for (int t = 0; t < IT; t++) {
        const float* tq = ts + t * 3 * PJ;
        float t00 = tq[r],     t01 = tq[PJ + r],     t02 = tq[2 * PJ + r];
        float t10 = tq[r + 8], t11 = tq[PJ + r + 8], t12 = tq[2 * PJ + r + 8];

        unsigned ah[16];
#pragma unroll
        for (int kt = 0; kt < 4; kt++) {
#pragma unroll
            for (int cp = 0; cp < 2; cp++) {
                int c0 = kt * 16 + kq + cp * 8;
                float4 wA = w0i[c0];
                float4 wB = w0i[c0 + 1];
                float va = fmaxf(fmaf(t00, wA.x, fmaf(t01, wA.y, fmaf(t02, wA.z, wA.w))), 0.f);
                float vb = fmaxf(fmaf(t00, wB.x, fmaf(t01, wB.y, fmaf(t02, wB.z, wB.w))), 0.f);
                float vc = fmaxf(fmaf(t10, wA.x, fmaf(t11, wA.y, fmaf(t12, wA.z, wA.w))), 0.f);
                float vd = fmaxf(fmaf(t10, wB.x, fmaf(t11, wB.y, fmaf(t12, wB.z, wB.w))), 0.f);
                ah[kt * 4 + cp * 2 + 0] = pack_bf2(va, vb);
                ah[kt * 4 + cp * 2 + 1] = pack_bf2(vc, vd);
            }
        }

        // MMA + epilogue per nf (B resident in regs)
        float outp00 = 0.f, outp01 = 0.f, outp10 = 0.f, outp11 = 0.f;
#pragma unroll
        for (int nf = 0; nf < 8; nf++) {
            float acc[4] = {0.f, 0.f, 0.f, 0.f};
#pragma unroll
            for (int kt = 0; kt < 4; kt++)
                mma16816(acc, &ah[kt * 4], bfr[nf][kt]);
            int c2 = nf * 4 + (lane & 3);           // pair index n0/2
            float4 w2v = w2i[c2];
            float2 b1v = b1i[c2];
            float ha = fmaxf(acc[0] + b1v.x, 0.f);
            float hb = fmaxf(acc[1] + b1v.y, 0.f);
            outp00 = fmaf(ha, w2v.x, fmaf(hb, w2v.y, outp00));
            outp01 = fmaf(ha, w2v.z, fmaf(hb, w2v.w, outp01));
            float hc = fmaxf(acc[2] + b1v.x, 0.f);
            float hd = fmaxf(acc[3] + b1v.y, 0.f);
            outp10 = fmaf(hc, w2v.x, fmaf(hd, w2v.y, outp10));
            outp11 = fmaf(hc, w2v.z, fmaf(hd, w2v.w, outp11));
        }
        // quad reduce over lane&3 (different n columns)
#pragma unroll
        for (int off = 1; off <= 2; off <<= 1) {
            outp00 += __shfl_xor_sync(0xffffffffu, outp00, off);
            outp01 += __shfl_xor_sync(0xffffffffu, outp01, off);
            outp10 += __shfl_xor_sync(0xffffffffu, outp10, off);
            outp11 += __shfl_xor_sync(0xffffffffu, outp11, off);
        }
        if ((lane & 3) == 0) {
            biasS[r * 2 + 0] = outp00;
            biasS[r * 2 + 1] = outp01;
            biasS[(r + 8) * 2 + 0] = outp10;
            biasS[(r + 8) * 2 + 1] = outp11;
        }
        __syncthreads();

        // softmax over j per head (no max subtraction; logits bounded small)
        float l = sim[t] + biasS[jj * 2 + eh];
        float ev = __expf(l);
        float sv = ev;
#pragma unroll
        for (int off = 16; off; off >>= 1)
            sv += __shfl_xor_sync(0xffffffffu, sv, off);
        if (lane == 0) red[w] = sv;
        __syncthreads();
        sv = red[eh * 4 + 0] + red[eh * 4 + 1] + red[eh * 4 + 2] + red[eh * 4 + 3];
        attns[t * 2 * PJ + eh * PJ + jj] = ev / sv;
    }
    __syncthreads();

    // ---- attn @ V : thread = (o = tid&127, query-half = tid>>7) ----
    {
        const int o = tid & 127, qh = tid >> 7, e = o >> 6;
        const ulonglong2* vrow = (const ulonglong2*)(g_v + (size_t)(bg * OFFD + o) * PJ);
        for (int t = qh * 4; t < qh * 4 + 4; t++) {
            const ulonglong2* arow = (const ulonglong2*)(attns + t * 2 * PJ + e * PJ);
            unsigned long long accA = 0ull, accB = 0ull;
#pragma unroll
            for (int q = 0; q < 32; q++) {
                ulonglong2 av = arow[q];
                ulonglong2 vv = vrow[q];
                accA = ffma2(av.x, vv.x, accA);
                accB = ffma2(av.y, vv.y, accB);
            }
            float2 fa = unpack2(accA), fb = unpack2(accB);
            g_att[(size_t)(b * INNER + g * OFFD + o) * PQ + i0 + t] =
                fa.x + fa.y + fb.x + fb.y;
        }
    }
}

// ============================================================
// Kernel E: output projection
// ============================================================
__global__ void k_oproj(const float* __restrict__ wo, const float* __restrict__ bo,
                        float* __restrict__ out) {
    const int p0 = blockIdx.x * 64;
    const int o0 = blockIdx.y * 64;
    const int b = blockIdx.z;
    const int tid = threadIdx.x;
    const int tx = tid & 15, ty = tid >> 4;

    __shared__ __align__(16) float As[16 * 64];
    __shared__ __align__(16) float Bs[16 * 64];

    float acc[4][4];
#pragma unroll
    for (int a = 0; a < 4; a++)
#pragma unroll
        for (int c = 0; c < 4; c++) acc[a][c] = 0.f;

    for (int k0 = 0; k0 < INNER; k0 += 16) {
        {
            int m = tid >> 2, kqq = (tid & 3) * 4;
            float4 wv = *(const float4*)(wo + (size_t)(o0 + m) * INNER + k0 + kqq);
            As[(kqq + 0) * 64 + m] = wv.x;
            As[(kqq + 1) * 64 + m] = wv.y;
            As[(kqq + 2) * 64 + m] = wv.z;
            As[(kqq + 3) * 64 + m] = wv.w;
            int k = tid >> 4, pq = (tid & 15) * 4;
            float4 bv = *(const float4*)(g_att + (size_t)(b * INNER + k0 + k) * PQ + p0 + pq);
            *(float4*)(Bs + k * 64 + pq) = bv;
        }
        __syncthreads();
#pragma unroll
        for (int k = 0; k < 16; k++) {
            float4 am = *(const float4*)(As + k * 64 + ty * 4);
            float4 bn = *(const float4*)(Bs + k * 64 + tx * 4);
            float a4[4] = {am.x, am.y, am.z, am.w};
            float b4[4] = {bn.x, bn.y, bn.z, bn.w};
#pragma unroll
            for (int a = 0; a < 4; a++)
#pragma unroll
                for (int c = 0; c < 4; c++) acc[a][c] = fmaf(a4[a], b4[c], acc[a][c]);
        }
        __syncthreads();
    }
#pragma unroll
    for (int a = 0; a < 4; a++) {
        float bias = bo[o0 + ty * 4 + a];
#pragma unroll
        for (int c = 0; c < 4; c++)
            out[(size_t)(b * DIMC + o0 + ty * 4 + a) * PQ + p0 + tx * 4 + c] =
                acc[a][c] + bias;
    }
}

// ============================================================
extern "C" void kernel_launch(void* const* d_in, const int* in_sizes, int n_in,
                              void* d_out, int out_size) {
    const float* x    = (const float*)d_in[0];
    const float* wq   = (const float*)d_in[1];
    const float* wk   = (const float*)d_in[2];
    const float* wv   = (const float*)d_in[3];
    const float* dww  = (const float*)d_in[4];
    const float* dwb  = (const float*)d_in[5];
    const float* pww  = (const float*)d_in[6];
    const float* cw0  = (const float*)d_in[7];
    const float* cb0  = (const float*)d_in[8];
    const float* cw1  = (const float*)d_in[9];
    const float* cb1  = (const float*)d_in[10];
    const float* cw2  = (const float*)d_in[11];
    const float* cb2  = (const float*)d_in[12];
    const float* wo   = (const float*)d_in[13];
    const float* bo   = (const float*)d_in[14];
    float* out = (float*)d_out;
    (void)cb2; // constant-per-head bias cancels in softmax

    k_qproj<<<dim3(PQ / 16, NBG), 128>>>(x, wq);
    k_offsets<<<dim3(PJ, NBG), 128>>>(dww, dwb, pww);
    k_sample_kv<<<dim3(PJ, NBG), 128>>>(x, wk, wv);
    k_attn<<<dim3(PQ / IT, NBG), 256>>>(cw0, cb0, cw1, cb1, cw2, cb2);
    k_oproj<<<dim3(PQ / 64, DIMC / 64, BB), 256>>>(wo, bo, out);
}

// round 5
// speedup vs baseline: 1.9638x; 1.0278x over previous
#include <cuda_runtime.h>
#include <cuda_bf16.h>
#include <math.h>

// ---------------- problem constants ----------------
#define BB 2
#define DIMC 256
#define GG 4
#define CHG 64          // DIM/GROUPS
#define OFFD 128
#define NBG 8           // B*GROUPS
#define FF 4
#define HH 16
#define WW 16
#define PQ 1024         // F*H*W
#define PJ 128          // FD*HD*WD
#define CPB 64
#define INNER 512
#define IT 8            // queries per block in kernel D
#define KP 66           // padded K stride (halves) for w1 smem

// ---------------- scratch ----------------
__device__ float g_q[NBG * OFFD * PQ];
__device__ float g_grid[NBG * PJ * 3];
__device__ float g_k[NBG * OFFD * PJ];
__device__ float g_v[NBG * OFFD * PJ];
__device__ float g_att[BB * INNER * PQ];

// ---------------- helpers ----------------
__device__ __forceinline__ unsigned long long ffma2(unsigned long long a,
                                                    unsigned long long b,
                                                    unsigned long long c) {
    unsigned long long d;
    asm("fma.rn.f32x2 %0, %1, %2, %3;" : "=l"(d) : "l"(a), "l"(b), "l"(c));
    return d;
}
__device__ __forceinline__ unsigned long long pack2(float lo, float hi) {
    unsigned long long d;
    asm("mov.b64 %0, {%1, %2};" : "=l"(d) : "f"(lo), "f"(hi));
    return d;
}
__device__ __forceinline__ float2 unpack2(unsigned long long v) {
    float2 r;
    asm("mov.b64 {%0, %1}, %2;" : "=f"(r.x), "=f"(r.y) : "l"(v));
    return r;
}
__device__ __forceinline__ void mma16816(float* c, const unsigned* a, const unsigned* b) {
    asm volatile(
        "mma.sync.aligned.m16n8k16.row.col.f32.bf16.bf16.f32 "
        "{%0,%1,%2,%3}, {%4,%5,%6,%7}, {%8,%9}, {%0,%1,%2,%3};"
        : "+f"(c[0]), "+f"(c[1]), "+f"(c[2]), "+f"(c[3])
        : "r"(a[0]), "r"(a[1]), "r"(a[2]), "r"(a[3]), "r"(b[0]), "r"(b[1]));
}
__device__ __forceinline__ unsigned pack_bf2(float a, float b) {
    __nv_bfloat162 t = __floats2bfloat162_rn(a, b);
    return *(unsigned*)&t;
}

// ============================================================
// Kernel A: grouped 1x1 conv -> q   (f32x2 packed inner loop)
// ============================================================
__global__ void k_qproj(const float* __restrict__ x, const float* __restrict__ wq) {
    const int bg = blockIdx.y;
    const int b = bg >> 2, g = bg & 3;
    const int p0 = blockIdx.x * 16;
    const int o = threadIdx.x;

    __shared__ __align__(16) float xs[CHG * 16];
    for (int e = threadIdx.x; e < CHG * 16; e += 128) {
        int i = e >> 4, p = e & 15;
        xs[e] = x[(size_t)(b * DIMC + g * CHG + i) * PQ + p0 + p];
    }
    __syncthreads();

    unsigned long long acc2[8];
#pragma unroll
    for (int q = 0; q < 8; q++) acc2[q] = 0ull;

    const float* wrow = wq + (size_t)(g * OFFD + o) * CHG;
#pragma unroll 8
    for (int i = 0; i < CHG; i++) {
        unsigned long long wv = pack2(wrow[i], wrow[i]);
        const unsigned long long* xr = (const unsigned long long*)(xs + i * 16);
#pragma unroll
        for (int q = 0; q < 8; q++) acc2[q] = ffma2(wv, xr[q], acc2[q]);
    }
    float* qout = g_q + (size_t)(bg * OFFD + o) * PQ + p0;
#pragma unroll
    for (int q = 0; q < 8; q++) {
        float2 f = unpack2(acc2[q]);
        qout[q * 2 + 0] = f.x;
        qout[q * 2 + 1] = f.y;
    }
}

// ============================================================
// Kernel B: offsets -> deformed grid coords
// ============================================================
__global__ void k_offsets(const float* __restrict__ dww, const float* __restrict__ dwb,
                          const float* __restrict__ pww) {
    const int pos = blockIdx.x;
    const int bg = blockIdx.y;
    const int c = threadIdx.x;
    const int lane = c & 31, wid = c >> 5;

    const int zo = pos >> 6;
    const int yo = (pos >> 3) & 7;
    const int xo = pos & 7;

    const float* qrow = g_q + (size_t)(bg * OFFD + c) * PQ;
    float acc = 0.f;
#pragma unroll
    for (int kz = 0; kz < 4; kz++) {
        int z = 2 * zo - 1 + kz;
        if (z < 0 || z >= FF) continue;
#pragma unroll
        for (int ky = 0; ky < 4; ky++) {
            int y = 2 * yo - 1 + ky;
            if (y < 0 || y >= HH) continue;
#pragma unroll
            for (int kx = 0; kx < 4; kx++) {
                int xx = 2 * xo - 1 + kx;
                if (xx < 0 || xx >= WW) continue;
                acc = fmaf(qrow[(z * HH + y) * WW + xx],
                           dww[c * 64 + (kz * 4 + ky) * 4 + kx], acc);
            }
        }
    }
    float v = acc + dwb[c];
    float act = 0.5f * v * (1.f + erff(v * 0.70710678118654752f));

    __shared__ float acts[OFFD];
    __shared__ float sred[3];
    acts[c] = act;
    __syncthreads();

    if (wid < 3) {
        float s = 0.f;
#pragma unroll
        for (int q = 0; q < 4; q++) {
            int cc = lane + q * 32;
            s = fmaf(acts[cc], pww[wid * OFFD + cc], s);
        }
#pragma unroll
        for (int off = 16; off; off >>= 1) s += __shfl_xor_sync(0xffffffffu, s, off);
        if (lane == 0) sred[wid] = s;
    }
    __syncthreads();

    if (c == 0) {
        float of = tanhf(sred[0]) * 2.0f;
        float oh = tanhf(sred[1]) * 2.0f;
        float ow = tanhf(sred[2]) * 2.0f;
        float gf = 2.0f * ((float)zo + of) / 1.0f - 1.0f;
        float gh = 2.0f * ((float)yo + oh) / 7.0f - 1.0f;
        float gw = 2.0f * ((float)xo + ow) / 7.0f - 1.0f;
        float* gp = g_grid + (size_t)(bg * PJ + pos) * 3;
        gp[0] = gf; gp[1] = gh; gp[2] = gw;
    }
}

// ============================================================
// Kernel C: trilinear grid-sample + k/v projections
// ============================================================
__global__ void k_sample_kv(const float* __restrict__ x, const float* __restrict__ wk,
                            const float* __restrict__ wv) {
    const int j = blockIdx.x;
    const int bg = blockIdx.y;
    const int b = bg >> 2, g = bg & 3;
    const int tid = threadIdx.x;

    const float* gp = g_grid + (size_t)(bg * PJ + j) * 3;
    const float g0 = gp[0], g1 = gp[1], g2 = gp[2];

    __shared__ float kvs[CHG];

    if (tid < CHG) {
        float ix = ((g0 + 1.f) * (float)WW - 1.f) * 0.5f;
        float iy = ((g1 + 1.f) * (float)HH - 1.f) * 0.5f;
        float iz = ((g2 + 1.f) * (float)FF - 1.f) * 0.5f;
        float fx0 = floorf(ix), fy0 = floorf(iy), fz0 = floorf(iz);
        float tx = ix - fx0, ty = iy - fy0, tz = iz - fz0;
        int x0 = (int)fx0, y0 = (int)fy0, z0 = (int)fz0;

        const float* xp = x + (size_t)(b * DIMC + g * CHG + tid) * PQ;
        float acc = 0.f;
#pragma unroll
        for (int dz = 0; dz < 2; dz++)
#pragma unroll
            for (int dy = 0; dy < 2; dy++)
#pragma unroll
                for (int dx = 0; dx < 2; dx++) {
                    int xc = x0 + dx, yc = y0 + dy, zc = z0 + dz;
                    float wgt = (dx ? tx : 1.f - tx) * (dy ? ty : 1.f - ty) *
                                (dz ? tz : 1.f - tz);
                    bool valid = (xc >= 0) & (xc < WW) & (yc >= 0) & (yc < HH) &
                                 (zc >= 0) & (zc < FF);
                    int xi = min(max(xc, 0), WW - 1);
                    int yi = min(max(yc, 0), HH - 1);
                    int zi = min(max(zc, 0), FF - 1);
                    float val = xp[(zi * HH + yi) * WW + xi];
                    acc += valid ? val * wgt : 0.f;
                }
        kvs[tid] = acc;
    }
    __syncthreads();

    float ak = 0.f, av = 0.f;
#pragma unroll
    for (int i = 0; i < CHG; i++) {
        float kv = kvs[i];
        ak = fmaf(wk[(g * OFFD + tid) * CHG + i], kv, ak);
        av = fmaf(wv[(g * OFFD + tid) * CHG + i], kv, av);
    }
    g_k[(size_t)(bg * OFFD + tid) * PJ + j] = ak;
    g_v[(size_t)(bg * OFFD + tid) * PJ + j] = av;
}

// ============================================================
// Kernel D v5: barrier-free query loop. sim lives in SMEM; MMA row-owner
// finishes exp + unnormalized attn + partial sums. 3 block barriers total.
// ============================================================
__global__ __launch_bounds__(256, 2)
void k_attn(const float* __restrict__ cw0, const float* __restrict__ cb0,
            const float* __restrict__ cw1, const float* __restrict__ cb1,
            const float* __restrict__ cw2, const float* __restrict__ cb2) {
    __shared__ __align__(16) __nv_bfloat16 w1h[CPB * KP];    // [n][k]
    __shared__ __align__(16) float ts[IT * 3 * PJ];          // [q][d][j]
    __shared__ __align__(16) float qs[OFFD * IT];            // [o][t] *scale
    __shared__ __align__(16) float attns[IT * 2 * PJ];       // [t][head][j] unnormalized
    __shared__ __align__(16) float simS[IT * 2 * PJ];        // [t][head][j]
    __shared__ __align__(16) float4 w0i[CPB];                // {w0_0,w0_1,w0_2,b0}
    __shared__ __align__(16) float4 w2i[CPB / 2];
    __shared__ __align__(16) float2 b1i[CPB / 2];
    __shared__ float sumP[IT * 2 * 8];                       // [t][head][warp]

    const int bg = blockIdx.y;
    const int b = bg >> 2, g = bg & 3;
    const int i0 = blockIdx.x * IT;
    const int tid = threadIdx.x;
    const int lane = tid & 31, w = tid >> 5;

    // ---- stage ----
    for (int e = tid; e < CPB * CPB; e += 256) {
        int k = e >> 6, n = e & 63;
        w1h[n * KP + k] = __float2bfloat16_rn(cw1[e]);
    }
    if (tid < CPB)
        w0i[tid] = make_float4(cw0[tid], cw0[64 + tid], cw0[128 + tid], cb0[tid]);
    if (tid < CPB / 2) {
        int c = tid * 2;
        w2i[tid] = make_float4(cw2[c * 2 + 0], cw2[c * 2 + 2],
                               cw2[c * 2 + 1], cw2[c * 2 + 3]);
        b1i[tid] = make_float2(cb1[c], cb1[c + 1]);
    }
    {
        int o = tid >> 1, half = (tid & 1) * 4;
        float4 qv = *(const float4*)(g_q + (size_t)(bg * OFFD + o) * PQ + i0 + half);
        qs[o * IT + half + 0] = qv.x * 0.125f;
        qs[o * IT + half + 1] = qv.y * 0.125f;
        qs[o * IT + half + 2] = qv.z * 0.125f;
        qs[o * IT + half + 3] = qv.w * 0.125f;
    }
    for (int e = tid; e < IT * 3 * PJ; e += 256) {
        int q = e / 384, rem = e - q * 384;
        int d = rem >> 7, j = rem & 127;
        int i = i0 + q;
        float gq;
        if (d == 0) gq = 2.0f * (float)(i >> 8) / 3.0f - 1.0f;
        else if (d == 1) gq = 2.0f * (float)((i >> 4) & 15) / 15.0f - 1.0f;
        else gq = 2.0f * (float)(i & 15) / 15.0f - 1.0f;
        float gj = g_grid[(size_t)(bg * PJ + j) * 3 + d];
        float p = gq - gj;
        ts[e] = copysignf(log1pf(fabsf(p)), p);
    }
    __syncthreads();                                     // barrier 1

    const int r = w * 16 + (lane >> 2);
    const int kq = (lane & 3) * 2;

    // ---- hoist w1 B-fragments into registers ----
    unsigned bfr[8][4][2];
#pragma unroll
    for (int nf = 0; nf < 8; nf++) {
        int nrow = nf * 8 + (lane >> 2);
#pragma unroll
        for (int kt = 0; kt < 4; kt++) {
            bfr[nf][kt][0] = *(const unsigned*)&w1h[nrow * KP + kt * 16 + kq];
            bfr[nf][kt][1] = *(const unsigned*)&w1h[nrow * KP + kt * 16 + kq + 8];
        }
    }

    // ---- sim -> smem (j-owner layout) ----
    {
        const int jj = tid & 127, eh = tid >> 7;
        float sim[IT];
#pragma unroll
        for (int t = 0; t < IT; t++) sim[t] = 0.f;
        const float* kb = g_k + (size_t)bg * OFFD * PJ + (size_t)eh * 64 * PJ + jj;
#pragma unroll 4
        for (int o = 0; o < 64; o++) {
            float kv = kb[o * PJ];
            float4 qa = *(const float4*)(qs + (eh * 64 + o) * IT);
            float4 qb = *(const float4*)(qs + (eh * 64 + o) * IT + 4);
            sim[0] = fmaf(qa.x, kv, sim[0]); sim[1] = fmaf(qa.y, kv, sim[1]);
            sim[2] = fmaf(qa.z, kv, sim[2]); sim[3] = fmaf(qa.w, kv, sim[3]);
            sim[4] = fmaf(qb.x, kv, sim[4]); sim[5] = fmaf(qb.y, kv, sim[5]);
            sim[6] = fmaf(qb.z, kv, sim[6]); sim[7] = fmaf(qb.w, kv, sim[7]);
        }
#pragma unroll
        for (int t = 0; t < IT; t++) simS[(t * 2 + eh) * PJ + jj] = sim[t];
    }
    __syncthreads();                                     // barrier 2

    // ---- per-query loop: NO block barriers ----
    for (int t = 0; t < IT; t++) {
        const float* tq = ts + t * 3 * PJ;
        float t00 = tq[r],     t01 = tq[PJ + r],     t02 = tq[2 * PJ + r];
        float t10 = tq[r + 8], t11 = tq[PJ + r + 8], t12 = tq[2 * PJ + r + 8];

        unsigned ah[16];
#pragma unroll
        for (int kt = 0; kt < 4; kt++) {
#pragma unroll
            for (int cp = 0; cp < 2; cp++) {
                int c0 = kt * 16 + kq + cp * 8;
                float4 wA = w0i[c0];
                float4 wB = w0i[c0 + 1];
                float va = fmaxf(fmaf(t00, wA.x, fmaf(t01, wA.y, fmaf(t02, wA.z, wA.w))), 0.f);
                float vb = fmaxf(fmaf(t00, wB.x, fmaf(t01, wB.y, fmaf(t02, wB.z, wB.w))), 0.f);
                float vc = fmaxf(fmaf(t10, wA.x, fmaf(t11, wA.y, fmaf(t12, wA.z, wA.w))), 0.f);
                float vd = fmaxf(fmaf(t10, wB.x, fmaf(t11, wB.y, fmaf(t12, wB.z, wB.w))), 0.f);
                ah[kt * 4 + cp * 2 + 0] = pack_bf2(va, vb);
                ah[kt * 4 + cp * 2 + 1] = pack_bf2(vc, vd);
            }
        }

        float outp00 = 0.f, outp01 = 0.f, outp10 = 0.f, outp11 = 0.f;
#pragma unroll
        for (int nf = 0; nf < 8; nf++) {
            float acc[4] = {0.f, 0.f, 0.f, 0.f};
#pragma unroll
            for (int kt = 0; kt < 4; kt++)
                mma16816(acc, &ah[kt * 4], bfr[nf][kt]);
            int c2 = nf * 4 + (lane & 3);
            float4 w2v = w2i[c2];
            float2 b1v = b1i[c2];
            float ha = fmaxf(acc[0] + b1v.x, 0.f);
            float hb = fmaxf(acc[1] + b1v.y, 0.f);
            outp00 = fmaf(ha, w2v.x, fmaf(hb, w2v.y, outp00));
            outp01 = fmaf(ha, w2v.z, fmaf(hb, w2v.w, outp01));
            float hc = fmaxf(acc[2] + b1v.x, 0.f);
            float hd = fmaxf(acc[3] + b1v.y, 0.f);
            outp10 = fmaf(hc, w2v.x, fmaf(hd, w2v.y, outp10));
            outp11 = fmaf(hc, w2v.z, fmaf(hd, w2v.w, outp11));
        }
        // quad butterfly: all lanes in quad get full bias
#pragma unroll
        for (int off = 1; off <= 2; off <<= 1) {
            outp00 += __shfl_xor_sync(0xffffffffu, outp00, off);
            outp01 += __shfl_xor_sync(0xffffffffu, outp01, off);
            outp10 += __shfl_xor_sync(0xffffffffu, outp10, off);
            outp11 += __shfl_xor_sync(0xffffffffu, outp11, off);
        }

        // unnormalized softmax numerators (logits are small; exp is safe)
        float e00 = __expf(simS[(t * 2 + 0) * PJ + r] + outp00);
        float e01 = __expf(simS[(t * 2 + 1) * PJ + r] + outp01);
        float e10 = __expf(simS[(t * 2 + 0) * PJ + r + 8] + outp10);
        float e11 = __expf(simS[(t * 2 + 1) * PJ + r + 8] + outp11);
        if ((lane & 3) == 0) {
            attns[(t * 2 + 0) * PJ + r] = e00;
            attns[(t * 2 + 1) * PJ + r] = e01;
            attns[(t * 2 + 0) * PJ + r + 8] = e10;
            attns[(t * 2 + 1) * PJ + r + 8] = e11;
        }
        // warp partial sums (lanes within a quad hold identical values)
        float s0 = e00 + e10, s1 = e01 + e11;
#pragma unroll
        for (int off = 4; off <= 16; off <<= 1) {
            s0 += __shfl_xor_sync(0xffffffffu, s0, off);
            s1 += __shfl_xor_sync(0xffffffffu, s1, off);
        }
        if (lane == 0) {
            sumP[(t * 2 + 0) * 8 + w] = s0;
            sumP[(t * 2 + 1) * 8 + w] = s1;
        }
    }
    __syncthreads();                                     // barrier 3

    // ---- attn @ V with deferred normalization ----
    {
        const int o = tid & 127, qh = tid >> 7, e = o >> 6;
        const ulonglong2* vrow = (const ulonglong2*)(g_v + (size_t)(bg * OFFD + o) * PJ);
        for (int t = qh * 4; t < qh * 4 + 4; t++) {
            const float* sp = sumP + (t * 2 + e) * 8;
            float S = ((sp[0] + sp[1]) + (sp[2] + sp[3])) +
                      ((sp[4] + sp[5]) + (sp[6] + sp[7]));
            const ulonglong2* arow = (const ulonglong2*)(attns + (t * 2 + e) * PJ);
            unsigned long long accA = 0ull, accB = 0ull;
#pragma unroll
            for (int q = 0; q < 32; q++) {
                ulonglong2 av = arow[q];
                ulonglong2 vv = vrow[q];
                accA = ffma2(av.x, vv.x, accA);
                accB = ffma2(av.y, vv.y, accB);
            }
            float2 fa = unpack2(accA), fb = unpack2(accB);
            g_att[(size_t)(b * INNER + g * OFFD + o) * PQ + i0 + t] =
                (fa.x + fa.y + fb.x + fb.y) / S;
        }
    }
}

// ============================================================
// Kernel E: output projection (f32x2 packed inner product)
// ============================================================
__global__ void k_oproj(const float* __restrict__ wo, const float* __restrict__ bo,
                        float* __restrict__ out) {
    const int p0 = blockIdx.x * 64;
    const int o0 = blockIdx.y * 64;
    const int b = blockIdx.z;
    const int tid = threadIdx.x;
    const int tx = tid & 15, ty = tid >> 4;

    __shared__ __align__(16) float As[16 * 64];
    __shared__ __align__(16) float Bs[16 * 64];

    unsigned long long acc2[4][2];
#pragma unroll
    for (int a = 0; a < 4; a++) { acc2[a][0] = 0ull; acc2[a][1] = 0ull; }

    for (int k0 = 0; k0 < INNER; k0 += 16) {
        {
            int m = tid >> 2, kqq = (tid & 3) * 4;
            float4 wv = *(const float4*)(wo + (size_t)(o0 + m) * INNER + k0 + kqq);
            As[(kqq + 0) * 64 + m] = wv.x;
            As[(kqq + 1) * 64 + m] = wv.y;
            As[(kqq + 2) * 64 + m] = wv.z;
            As[(kqq + 3) * 64 + m] = wv.w;
            int k = tid >> 4, pq = (tid & 15) * 4;
            float4 bv = *(const float4*)(g_att + (size_t)(b * INNER + k0 + k) * PQ + p0 + pq);
            *(float4*)(Bs + k * 64 + pq) = bv;
        }
        __syncthreads();
#pragma unroll
        for (int k = 0; k < 16; k++) {
            float4 am = *(const float4*)(As + k * 64 + ty * 4);
            const unsigned long long* bn =
                (const unsigned long long*)(Bs + k * 64 + tx * 4);
            unsigned long long b0 = bn[0], b1 = bn[1];
            unsigned long long a0 = pack2(am.x, am.x);
            unsigned long long a1 = pack2(am.y, am.y);
            unsigned long long a2 = pack2(am.z, am.z);
            unsigned long long a3 = pack2(am.w, am.w);
            acc2[0][0] = ffma2(a0, b0, acc2[0][0]); acc2[0][1] = ffma2(a0, b1, acc2[0][1]);
            acc2[1][0] = ffma2(a1, b0, acc2[1][0]); acc2[1][1] = ffma2(a1, b1, acc2[1][1]);
            acc2[2][0] = ffma2(a2, b0, acc2[2][0]); acc2[2][1] = ffma2(a2, b1, acc2[2][1]);
            acc2[3][0] = ffma2(a3, b0, acc2[3][0]); acc2[3][1] = ffma2(a3, b1, acc2[3][1]);
        }
        __syncthreads();
    }
#pragma unroll
    for (int a = 0; a < 4; a++) {
        float bias = bo[o0 + ty * 4 + a];
        float2 c0 = unpack2(acc2[a][0]);
        float2 c1 = unpack2(acc2[a][1]);
        float* op = out + (size_t)(b * DIMC + o0 + ty * 4 + a) * PQ + p0 + tx * 4;
        op[0] = c0.x + bias;
        op[1] = c0.y + bias;
        op[2] = c1.x + bias;
        op[3] = c1.y + bias;
    }
}

// ============================================================
extern "C" void kernel_launch(void* const* d_in, const int* in_sizes, int n_in,
                              void* d_out, int out_size) {
    const float* x    = (const float*)d_in[0];
    const float* wq   = (const float*)d_in[1];
    const float* wk   = (const float*)d_in[2];
    const float* wv   = (const float*)d_in[3];
    const float* dww  = (const float*)d_in[4];
    const float* dwb  = (const float*)d_in[5];
    const float* pww  = (const float*)d_in[6];
    const float* cw0  = (const float*)d_in[7];
    const float* cb0  = (const float*)d_in[8];
    const float* cw1  = (const float*)d_in[9];
    const float* cb1  = (const float*)d_in[10];
    const float* cw2  = (const float*)d_in[11];
    const float* cb2  = (const float*)d_in[12];
    const float* wo   = (const float*)d_in[13];
    const float* bo   = (const float*)d_in[14];
    float* out = (float*)d_out;
    (void)cb2; // per-head constant bias cancels in softmax

    k_qproj<<<dim3(PQ / 16, NBG), 128>>>(x, wq);
    k_offsets<<<dim3(PJ, NBG), 128>>>(dww, dwb, pww);
    k_sample_kv<<<dim3(PJ, NBG), 128>>>(x, wk, wv);
    k_attn<<<dim3(PQ / IT, NBG), 256>>>(cw0, cb0, cw1, cb1, cw2, cb2);
    k_oproj<<<dim3(PQ / 64, DIMC / 64, BB), 256>>>(wo, bo, out);
}

// round 6
// speedup vs baseline: 2.0378x; 1.0377x over previous
#include <cuda_runtime.h>
#include <cuda_bf16.h>
#include <math.h>

// ---------------- problem constants ----------------
#define BB 2
#define DIMC 256
#define GG 4
#define CHG 64          // DIM/GROUPS
#define OFFD 128
#define NBG 8           // B*GROUPS
#define FF 4
#define HH 16
#define WW 16
#define PQ 1024         // F*H*W
#define PJ 128          // FD*HD*WD
#define CPB 64
#define INNER 512
#define IT 8            // queries per block in kernel D
#define KP 66           // padded K stride (halves) for w1 smem

// ---------------- scratch ----------------
__device__ float g_q[NBG * OFFD * PQ];
__device__ float g_grid[NBG * PJ * 3];
__device__ float g_k[NBG * OFFD * PJ];
__device__ float g_v[NBG * OFFD * PJ];
__device__ float g_att[BB * INNER * PQ];

// ---------------- helpers ----------------
__device__ __forceinline__ unsigned long long ffma2(unsigned long long a,
                                                    unsigned long long b,
                                                    unsigned long long c) {
    unsigned long long d;
    asm("fma.rn.f32x2 %0, %1, %2, %3;" : "=l"(d) : "l"(a), "l"(b), "l"(c));
    return d;
}
__device__ __forceinline__ unsigned long long pack2(float lo, float hi) {
    unsigned long long d;
    asm("mov.b64 %0, {%1, %2};" : "=l"(d) : "f"(lo), "f"(hi));
    return d;
}
__device__ __forceinline__ float2 unpack2(unsigned long long v) {
    float2 r;
    asm("mov.b64 {%0, %1}, %2;" : "=f"(r.x), "=f"(r.y) : "l"(v));
    return r;
}
__device__ __forceinline__ void mma16816(float* c, const unsigned* a, const unsigned* b) {
    asm volatile(
        "mma.sync.aligned.m16n8k16.row.col.f32.bf16.bf16.f32 "
        "{%0,%1,%2,%3}, {%4,%5,%6,%7}, {%8,%9}, {%0,%1,%2,%3};"
        : "+f"(c[0]), "+f"(c[1]), "+f"(c[2]), "+f"(c[3])
        : "r"(a[0]), "r"(a[1]), "r"(a[2]), "r"(a[3]), "r"(b[0]), "r"(b[1]));
}
// packed bf16x2 math
__device__ __forceinline__ unsigned hfma2(unsigned a, unsigned b, unsigned c) {
    unsigned d;
    asm("fma.rn.bf16x2 %0, %1, %2, %3;" : "=r"(d) : "r"(a), "r"(b), "r"(c));
    return d;
}
__device__ __forceinline__ unsigned hadd2(unsigned a, unsigned b) {
    unsigned d;
    asm("add.rn.bf16x2 %0, %1, %2;" : "=r"(d) : "r"(a), "r"(b));
    return d;
}
__device__ __forceinline__ unsigned hmax2z(unsigned a) {
    unsigned d;
    asm("max.bf16x2 %0, %1, %2;" : "=r"(d) : "r"(a), "r"(0u));
    return d;
}
// pack {lo, hi} floats -> bf16x2 (one CVT)
__device__ __forceinline__ unsigned packcvt(float lo, float hi) {
    unsigned d;
    asm("cvt.rn.bf16x2.f32 %0, %1, %2;" : "=r"(d) : "f"(hi), "f"(lo));
    return d;
}
__device__ __forceinline__ unsigned bcastbf(float x) {
    unsigned d;
    asm("cvt.rn.bf16x2.f32 %0, %1, %1;" : "=r"(d) : "f"(x));
    return d;
}

// ============================================================
// Kernel A: grouped 1x1 conv -> q   (f32x2 packed inner loop)
// ============================================================
__global__ void k_qproj(const float* __restrict__ x, const float* __restrict__ wq) {
    const int bg = blockIdx.y;
    const int b = bg >> 2, g = bg & 3;
    const int p0 = blockIdx.x * 16;
    const int o = threadIdx.x;

    __shared__ __align__(16) float xs[CHG * 16];
    for (int e = threadIdx.x; e < CHG * 16; e += 128) {
        int i = e >> 4, p = e & 15;
        xs[e] = x[(size_t)(b * DIMC + g * CHG + i) * PQ + p0 + p];
    }
    __syncthreads();

    unsigned long long acc2[8];
#pragma unroll
    for (int q = 0; q < 8; q++) acc2[q] = 0ull;

    const float* wrow = wq + (size_t)(g * OFFD + o) * CHG;
#pragma unroll 8
    for (int i = 0; i < CHG; i++) {
        unsigned long long wv = pack2(wrow[i], wrow[i]);
        const unsigned long long* xr = (const unsigned long long*)(xs + i * 16);
#pragma unroll
        for (int q = 0; q < 8; q++) acc2[q] = ffma2(wv, xr[q], acc2[q]);
    }
    float* qout = g_q + (size_t)(bg * OFFD + o) * PQ + p0;
#pragma unroll
    for (int q = 0; q < 8; q++) {
        float2 f = unpack2(acc2[q]);
        qout[q * 2 + 0] = f.x;
        qout[q * 2 + 1] = f.y;
    }
}

// ============================================================
// Kernel B: offsets -> deformed grid coords
// ============================================================
__global__ void k_offsets(const float* __restrict__ dww, const float* __restrict__ dwb,
                          const float* __restrict__ pww) {
    const int pos = blockIdx.x;
    const int bg = blockIdx.y;
    const int c = threadIdx.x;
    const int lane = c & 31, wid = c >> 5;

    const int zo = pos >> 6;
    const int yo = (pos >> 3) & 7;
    const int xo = pos & 7;

    const float* qrow = g_q + (size_t)(bg * OFFD + c) * PQ;
    float acc = 0.f;
#pragma unroll
    for (int kz = 0; kz < 4; kz++) {
        int z = 2 * zo - 1 + kz;
        if (z < 0 || z >= FF) continue;
#pragma unroll
        for (int ky = 0; ky < 4; ky++) {
            int y = 2 * yo - 1 + ky;
            if (y < 0 || y >= HH) continue;
#pragma unroll
            for (int kx = 0; kx < 4; kx++) {
                int xx = 2 * xo - 1 + kx;
                if (xx < 0 || xx >= WW) continue;
                acc = fmaf(qrow[(z * HH + y) * WW + xx],
                           dww[c * 64 + (kz * 4 + ky) * 4 + kx], acc);
            }
        }
    }
    float v = acc + dwb[c];
    float act = 0.5f * v * (1.f + erff(v * 0.70710678118654752f));

    __shared__ float acts[OFFD];
    __shared__ float sred[3];
    acts[c] = act;
    __syncthreads();

    if (wid < 3) {
        float s = 0.f;
#pragma unroll
        for (int q = 0; q < 4; q++) {
            int cc = lane + q * 32;
            s = fmaf(acts[cc], pww[wid * OFFD + cc], s);
        }
#pragma unroll
        for (int off = 16; off; off >>= 1) s += __shfl_xor_sync(0xffffffffu, s, off);
        if (lane == 0) sred[wid] = s;
    }
    __syncthreads();

    if (c == 0) {
        float of = tanhf(sred[0]) * 2.0f;
        float oh = tanhf(sred[1]) * 2.0f;
        float ow = tanhf(sred[2]) * 2.0f;
        float gf = 2.0f * ((float)zo + of) / 1.0f - 1.0f;
        float gh = 2.0f * ((float)yo + oh) / 7.0f - 1.0f;
        float gw = 2.0f * ((float)xo + ow) / 7.0f - 1.0f;
        float* gp = g_grid + (size_t)(bg * PJ + pos) * 3;
        gp[0] = gf; gp[1] = gh; gp[2] = gw;
    }
}

// ============================================================
// Kernel C: trilinear grid-sample + k/v projections
// ============================================================
__global__ void k_sample_kv(const float* __restrict__ x, const float* __restrict__ wk,
                            const float* __restrict__ wv) {
    const int j = blockIdx.x;
    const int bg = blockIdx.y;
    const int b = bg >> 2, g = bg & 3;
    const int tid = threadIdx.x;

    const float* gp = g_grid + (size_t)(bg * PJ + j) * 3;
    const float g0 = gp[0], g1 = gp[1], g2 = gp[2];

    __shared__ float kvs[CHG];

    if (tid < CHG) {
        float ix = ((g0 + 1.f) * (float)WW - 1.f) * 0.5f;
        float iy = ((g1 + 1.f) * (float)HH - 1.f) * 0.5f;
        float iz = ((g2 + 1.f) * (float)FF - 1.f) * 0.5f;
        float fx0 = floorf(ix), fy0 = floorf(iy), fz0 = floorf(iz);
        float tx = ix - fx0, ty = iy - fy0, tz = iz - fz0;
        int x0 = (int)fx0, y0 = (int)fy0, z0 = (int)fz0;

        const float* xp = x + (size_t)(b * DIMC + g * CHG + tid) * PQ;
        float acc = 0.f;
#pragma unroll
        for (int dz = 0; dz < 2; dz++)
#pragma unroll
            for (int dy = 0; dy < 2; dy++)
#pragma unroll
                for (int dx = 0; dx < 2; dx++) {
                    int xc = x0 + dx, yc = y0 + dy, zc = z0 + dz;
                    float wgt = (dx ? tx : 1.f - tx) * (dy ? ty : 1.f - ty) *
                                (dz ? tz : 1.f - tz);
                    bool valid = (xc >= 0) & (xc < WW) & (yc >= 0) & (yc < HH) &
                                 (zc >= 0) & (zc < FF);
                    int xi = min(max(xc, 0), WW - 1);
                    int yi = min(max(yc, 0), HH - 1);
                    int zi = min(max(zc, 0), FF - 1);
                    float val = xp[(zi * HH + yi) * WW + xi];
                    acc += valid ? val * wgt : 0.f;
                }
        kvs[tid] = acc;
    }
    __syncthreads();

    float ak = 0.f, av = 0.f;
#pragma unroll
    for (int i = 0; i < CHG; i++) {
        float kv = kvs[i];
        ak = fmaf(wk[(g * OFFD + tid) * CHG + i], kv, ak);
        av = fmaf(wv[(g * OFFD + tid) * CHG + i], kv, av);
    }
    g_k[(size_t)(bg * OFFD + tid) * PJ + j] = ak;
    g_v[(size_t)(bg * OFFD + tid) * PJ + j] = av;
}

// ============================================================
// Kernel D v6: bf16x2 A-gen + dual back-to-back MMA (layer1 64x64 and
// layer2 64x2 both on tensor cores). No quad reductions.
// ============================================================
__global__ __launch_bounds__(256, 2)
void k_attn(const float* __restrict__ cw0, const float* __restrict__ cb0,
            const float* __restrict__ cw1, const float* __restrict__ cb1,
            const float* __restrict__ cw2, const float* __restrict__ cb2) {
    __shared__ __align__(16) __nv_bfloat16 w1h[CPB * KP];    // [n][k]
    __shared__ __align__(16) float ts[IT * 3 * PJ];          // [q][d][j]
    __shared__ __align__(16) float qs[OFFD * IT];            // [o][t] *scale
    __shared__ __align__(16) float attns[IT * 2 * PJ];       // [t][head][j] unnormalized
    __shared__ __align__(16) float simS[IT * 2 * PJ];        // [t][head][j]
    __shared__ __align__(16) uint4 w0p[32];                  // packed {w0_0,w0_1,w0_2,b0} bf16x2 pairs
    __shared__ float w2s[CPB * 2], b1s[CPB];
    __shared__ float sumP[IT * 2 * 8];                       // [t][head][warp]

    const int bg = blockIdx.y;
    const int b = bg >> 2, g = bg & 3;
    const int i0 = blockIdx.x * IT;
    const int tid = threadIdx.x;
    const int lane = tid & 31, w = tid >> 5;

    // ---- stage ----
    for (int e = tid; e < CPB * CPB; e += 256) {
        int k = e >> 6, n = e & 63;
        w1h[n * KP + k] = __float2bfloat16_rn(cw1[e]);
    }
    if (tid < 32) {
        int c = tid * 2;
        uint4 wp;
        wp.x = packcvt(cw0[c], cw0[c + 1]);
        wp.y = packcvt(cw0[64 + c], cw0[64 + c + 1]);
        wp.z = packcvt(cw0[128 + c], cw0[128 + c + 1]);
        wp.w = packcvt(cb0[c], cb0[c + 1]);
        w0p[tid] = wp;
    }
    if (tid >= 64 && tid < 192) w2s[tid - 64] = cw2[tid - 64];
    if (tid >= 192) b1s[tid - 192] = cb1[tid - 192];
    {
        int o = tid >> 1, half = (tid & 1) * 4;
        float4 qv = *(const float4*)(g_q + (size_t)(bg * OFFD + o) * PQ + i0 + half);
        qs[o * IT + half + 0] = qv.x * 0.125f;
        qs[o * IT + half + 1] = qv.y * 0.125f;
        qs[o * IT + half + 2] = qv.z * 0.125f;
        qs[o * IT + half + 3] = qv.w * 0.125f;
    }
    for (int e = tid; e < IT * 3 * PJ; e += 256) {
        int q = e / 384, rem = e - q * 384;
        int d = rem >> 7, j = rem & 127;
        int i = i0 + q;
        float gq;
        if (d == 0) gq = 2.0f * (float)(i >> 8) / 3.0f - 1.0f;
        else if (d == 1) gq = 2.0f * (float)((i >> 4) & 15) / 15.0f - 1.0f;
        else gq = 2.0f * (float)(i & 15) / 15.0f - 1.0f;
        float gj = g_grid[(size_t)(bg * PJ + j) * 3 + d];
        float p = gq - gj;
        ts[e] = copysignf(log1pf(fabsf(p)), p);
    }
    __syncthreads();                                     // barrier 1

    const int r = w * 16 + (lane >> 2);
    const int q2 = lane & 3;
    const int kq = q2 * 2;
    const int nl = lane >> 2;

    // ---- hoist w1 B-fragments (layer1) ----
    unsigned bfr[8][4][2];
#pragma unroll
    for (int nf = 0; nf < 8; nf++) {
        int nrow = nf * 8 + nl;
#pragma unroll
        for (int kt = 0; kt < 4; kt++) {
            bfr[nf][kt][0] = *(const unsigned*)&w1h[nrow * KP + kt * 16 + kq];
            bfr[nf][kt][1] = *(const unsigned*)&w1h[nrow * KP + kt * 16 + kq + 8];
        }
    }
    // ---- layer2 B-fragments (w2: [k=64][head]; cols>=2 zero) + b1 packs ----
    unsigned bw2[4][2], b1p[4][2];
#pragma unroll
    for (int kt2 = 0; kt2 < 4; kt2++) {
        int k0 = kt2 * 16 + kq;
        bw2[kt2][0] = (nl < 2) ? packcvt(w2s[k0 * 2 + nl], w2s[(k0 + 1) * 2 + nl]) : 0u;
        bw2[kt2][1] = (nl < 2) ? packcvt(w2s[(k0 + 8) * 2 + nl], w2s[(k0 + 9) * 2 + nl]) : 0u;
        b1p[kt2][0] = packcvt(b1s[k0], b1s[k0 + 1]);
        b1p[kt2][1] = packcvt(b1s[k0 + 8], b1s[k0 + 9]);
    }

    // ---- sim -> smem (j-owner layout), f32x2 ----
    {
        const int jj = tid & 127, eh = tid >> 7;
        unsigned long long sim2[4] = {0ull, 0ull, 0ull, 0ull};
        const float* kb = g_k + (size_t)bg * OFFD * PJ + (size_t)eh * 64 * PJ + jj;
#pragma unroll 4
        for (int o = 0; o < 64; o++) {
            float kv = kb[o * PJ];
            unsigned long long kvp = pack2(kv, kv);
            const unsigned long long* qp =
                (const unsigned long long*)(qs + (eh * 64 + o) * IT);
            sim2[0] = ffma2(qp[0], kvp, sim2[0]);
            sim2[1] = ffma2(qp[1], kvp, sim2[1]);
            sim2[2] = ffma2(qp[2], kvp, sim2[2]);
            sim2[3] = ffma2(qp[3], kvp, sim2[3]);
        }
#pragma unroll
        for (int h2 = 0; h2 < 4; h2++) {
            float2 f = unpack2(sim2[h2]);
            simS[((2 * h2 + 0) * 2 + eh) * PJ + jj] = f.x;
            simS[((2 * h2 + 1) * 2 + eh) * PJ + jj] = f.y;
        }
    }
    __syncthreads();                                     // barrier 2

    // ---- per-query loop (no block barriers) ----
    for (int t = 0; t < IT; t++) {
        const float* tq = ts + t * 3 * PJ;
        unsigned tp0[3], tp1[3];
#pragma unroll
        for (int d = 0; d < 3; d++) {
            tp0[d] = bcastbf(tq[d * PJ + r]);
            tp1[d] = bcastbf(tq[d * PJ + r + 8]);
        }

        // A-gen: h0 fragment directly in bf16x2
        unsigned ah[16];
#pragma unroll
        for (int kt = 0; kt < 4; kt++) {
#pragma unroll
            for (int cp = 0; cp < 2; cp++) {
                uint4 W = w0p[kt * 8 + q2 + cp * 4];
                ah[kt * 4 + cp * 2 + 0] =
                    hmax2z(hfma2(tp0[0], W.x, hfma2(tp0[1], W.y, hfma2(tp0[2], W.z, W.w))));
                ah[kt * 4 + cp * 2 + 1] =
                    hmax2z(hfma2(tp1[0], W.x, hfma2(tp1[1], W.y, hfma2(tp1[2], W.z, W.w))));
            }
        }

        // layer1 MMA (paired nf for the layer2 k-tiles) + layer2 MMA
        float acc2[4] = {0.f, 0.f, 0.f, 0.f};
#pragma unroll
        for (int kt2 = 0; kt2 < 4; kt2++) {
            float accA[4] = {0.f, 0.f, 0.f, 0.f};
            float accB[4] = {0.f, 0.f, 0.f, 0.f};
#pragma unroll
            for (int kt = 0; kt < 4; kt++) {
                mma16816(accA, &ah[kt * 4], bfr[2 * kt2][kt]);
                mma16816(accB, &ah[kt * 4], bfr[2 * kt2 + 1][kt]);
            }
            unsigned a2[4];
            a2[0] = hmax2z(hadd2(packcvt(accA[0], accA[1]), b1p[kt2][0]));
            a2[1] = hmax2z(hadd2(packcvt(accA[2], accA[3]), b1p[kt2][0]));
            a2[2] = hmax2z(hadd2(packcvt(accB[0], accB[1]), b1p[kt2][1]));
            a2[3] = hmax2z(hadd2(packcvt(accB[2], accB[3]), b1p[kt2][1]));
            mma16816(acc2, a2, bw2[kt2]);
        }
        // acc2 (q2==0): {(r,h0), (r,h1), (r+8,h0), (r+8,h1)}

        float e00 = __expf(simS[(t * 2 + 0) * PJ + r] + acc2[0]);
        float e01 = __expf(simS[(t * 2 + 1) * PJ + r] + acc2[1]);
        float e10 = __expf(simS[(t * 2 + 0) * PJ + r + 8] + acc2[2]);
        float e11 = __expf(simS[(t * 2 + 1) * PJ + r + 8] + acc2[3]);
        if (q2 == 0) {
            attns[(t * 2 + 0) * PJ + r] = e00;
            attns[(t * 2 + 1) * PJ + r] = e01;
            attns[(t * 2 + 0) * PJ + r + 8] = e10;
            attns[(t * 2 + 1) * PJ + r + 8] = e11;
        }
        float s0 = e00 + e10, s1 = e01 + e11;
#pragma unroll
        for (int off = 4; off <= 16; off <<= 1) {
            s0 += __shfl_xor_sync(0xffffffffu, s0, off);
            s1 += __shfl_xor_sync(0xffffffffu, s1, off);
        }
        if (lane == 0) {
            sumP[(t * 2 + 0) * 8 + w] = s0;
            sumP[(t * 2 + 1) * 8 + w] = s1;
        }
    }
    __syncthreads();                                     // barrier 3

    // ---- attn @ V with deferred normalization ----
    {
        const int o = tid & 127, qh = tid >> 7, e = o >> 6;
        const ulonglong2* vrow = (const ulonglong2*)(g_v + (size_t)(bg * OFFD + o) * PJ);
        for (int t = qh * 4; t < qh * 4 + 4; t++) {
            const float* sp = sumP + (t * 2 + e) * 8;
            float S = ((sp[0] + sp[1]) + (sp[2] + sp[3])) +
                      ((sp[4] + sp[5]) + (sp[6] + sp[7]));
            const ulonglong2* arow = (const ulonglong2*)(attns + (t * 2 + e) * PJ);
            unsigned long long accA = 0ull, accB = 0ull;
#pragma unroll
            for (int q = 0; q < 32; q++) {
                ulonglong2 av = arow[q];
                ulonglong2 vv = vrow[q];
                accA = ffma2(av.x, vv.x, accA);
                accB = ffma2(av.y, vv.y, accB);
            }
            float2 fa = unpack2(accA), fb = unpack2(accB);
            g_att[(size_t)(b * INNER + g * OFFD + o) * PQ + i0 + t] =
                (fa.x + fa.y + fb.x + fb.y) / S;
        }
    }
}

// ============================================================
// Kernel E: output projection (f32x2 packed inner product)
// ============================================================
__global__ void k_oproj(const float* __restrict__ wo, const float* __restrict__ bo,
                        float* __restrict__ out) {
    const int p0 = blockIdx.x * 64;
    const int o0 = blockIdx.y * 64;
    const int b = blockIdx.z;
    const int tid = threadIdx.x;
    const int tx = tid & 15, ty = tid >> 4;

    __shared__ __align__(16) float As[16 * 64];
    __shared__ __align__(16) float Bs[16 * 64];

    unsigned long long acc2[4][2];
#pragma unroll
    for (int a = 0; a < 4; a++) { acc2[a][0] = 0ull; acc2[a][1] = 0ull; }

    for (int k0 = 0; k0 < INNER; k0 += 16) {
        {
            int m = tid >> 2, kqq = (tid & 3) * 4;
            float4 wv = *(const float4*)(wo + (size_t)(o0 + m) * INNER + k0 + kqq);
            As[(kqq + 0) * 64 + m] = wv.x;
            As[(kqq + 1) * 64 + m] = wv.y;
            As[(kqq + 2) * 64 + m] = wv.z;
            As[(kqq + 3) * 64 + m] = wv.w;
            int k = tid >> 4, pq = (tid & 15) * 4;
            float4 bv = *(const float4*)(g_att + (size_t)(b * INNER + k0 + k) * PQ + p0 + pq);
            *(float4*)(Bs + k * 64 + pq) = bv;
        }
        __syncthreads();
#pragma unroll
        for (int k = 0; k < 16; k++) {
            float4 am = *(const float4*)(As + k * 64 + ty * 4);
            const unsigned long long* bn =
                (const unsigned long long*)(Bs + k * 64 + tx * 4);
            unsigned long long b0 = bn[0], b1 = bn[1];
            unsigned long long a0 = pack2(am.x, am.x);
            unsigned long long a1 = pack2(am.y, am.y);
            unsigned long long a2 = pack2(am.z, am.z);
            unsigned long long a3 = pack2(am.w, am.w);
            acc2[0][0] = ffma2(a0, b0, acc2[0][0]); acc2[0][1] = ffma2(a0, b1, acc2[0][1]);
            acc2[1][0] = ffma2(a1, b0, acc2[1][0]); acc2[1][1] = ffma2(a1, b1, acc2[1][1]);
            acc2[2][0] = ffma2(a2, b0, acc2[2][0]); acc2[2][1] = ffma2(a2, b1, acc2[2][1]);
            acc2[3][0] = ffma2(a3, b0, acc2[3][0]); acc2[3][1] = ffma2(a3, b1, acc2[3][1]);
        }
        __syncthreads();
    }
#pragma unroll
    for (int a = 0; a < 4; a++) {
        float bias = bo[o0 + ty * 4 + a];
        float2 c0 = unpack2(acc2[a][0]);
        float2 c1 = unpack2(acc2[a][1]);
        float* op = out + (size_t)(b * DIMC + o0 + ty * 4 + a) * PQ + p0 + tx * 4;
        op[0] = c0.x + bias;
        op[1] = c0.y + bias;
        op[2] = c1.x + bias;
        op[3] = c1.y + bias;
    }
}

// ============================================================
extern "C" void kernel_launch(void* const* d_in, const int* in_sizes, int n_in,
                              void* d_out, int out_size) {
    const float* x    = (const float*)d_in[0];
    const float* wq   = (const float*)d_in[1];
    const float* wk   = (const float*)d_in[2];
    const float* wv   = (const float*)d_in[3];
    const float* dww  = (const float*)d_in[4];
    const float* dwb  = (const float*)d_in[5];
    const float* pww  = (const float*)d_in[6];
    const float* cw0  = (const float*)d_in[7];
    const float* cb0  = (const float*)d_in[8];
    const float* cw1  = (const float*)d_in[9];
    const float* cb1  = (const float*)d_in[10];
    const float* cw2  = (const float*)d_in[11];
    const float* cb2  = (const float*)d_in[12];
    const float* wo   = (const float*)d_in[13];
    const float* bo   = (const float*)d_in[14];
    float* out = (float*)d_out;
    (void)cb2; // per-head constant bias cancels in softmax

    k_qproj<<<dim3(PQ / 16, NBG), 128>>>(x, wq);
    k_offsets<<<dim3(PJ, NBG), 128>>>(dww, dwb, pww);
    k_sample_kv<<<dim3(PJ, NBG), 128>>>(x, wk, wv);
    k_attn<<<dim3(PQ / IT, NBG), 256>>>(cw0, cb0, cw1, cb1, cw2, cb2);
    k_oproj<<<dim3(PQ / 64, DIMC / 64, BB), 256>>>(wo, bo, out);
}

// round 7
// speedup vs baseline: 2.3409x; 1.1487x over previous
#include <cuda_runtime.h>
#include <cuda_bf16.h>
#include <math.h>

// ---------------- problem constants ----------------
#define BB 2
#define DIMC 256
#define GG 4
#define CHG 64          // DIM/GROUPS
#define OFFD 128
#define NBG 8           // B*GROUPS
#define FF 4
#define HH 16
#define WW 16
#define PQ 1024         // F*H*W
#define PJ 128          // FD*HD*WD
#define CPB 64
#define INNER 512
#define IT 8            // queries per block in kernel D
#define KP 66           // padded K stride (halves) for w1 smem

// ---------------- scratch ----------------
__device__ float g_q[NBG * OFFD * PQ];
__device__ float g_qT[NBG * PQ * OFFD];   // transposed copy: [bg][p][c]
__device__ float g_grid[NBG * PJ * 3];
__device__ float g_k[NBG * OFFD * PJ];
__device__ float g_v[NBG * OFFD * PJ];
__device__ float g_att[BB * INNER * PQ];

// ---------------- helpers ----------------
__device__ __forceinline__ unsigned long long ffma2(unsigned long long a,
                                                    unsigned long long b,
                                                    unsigned long long c) {
    unsigned long long d;
    asm("fma.rn.f32x2 %0, %1, %2, %3;" : "=l"(d) : "l"(a), "l"(b), "l"(c));
    return d;
}
__device__ __forceinline__ unsigned long long pack2(float lo, float hi) {
    unsigned long long d;
    asm("mov.b64 %0, {%1, %2};" : "=l"(d) : "f"(lo), "f"(hi));
    return d;
}
__device__ __forceinline__ float2 unpack2(unsigned long long v) {
    float2 r;
    asm("mov.b64 {%0, %1}, %2;" : "=f"(r.x), "=f"(r.y) : "l"(v));
    return r;
}
__device__ __forceinline__ void mma16816(float* c, const unsigned* a, const unsigned* b) {
    asm volatile(
        "mma.sync.aligned.m16n8k16.row.col.f32.bf16.bf16.f32 "
        "{%0,%1,%2,%3}, {%4,%5,%6,%7}, {%8,%9}, {%0,%1,%2,%3};"
        : "+f"(c[0]), "+f"(c[1]), "+f"(c[2]), "+f"(c[3])
        : "r"(a[0]), "r"(a[1]), "r"(a[2]), "r"(a[3]), "r"(b[0]), "r"(b[1]));
}
__device__ __forceinline__ unsigned hfma2(unsigned a, unsigned b, unsigned c) {
    unsigned d;
    asm("fma.rn.bf16x2 %0, %1, %2, %3;" : "=r"(d) : "r"(a), "r"(b), "r"(c));
    return d;
}
__device__ __forceinline__ unsigned hadd2(unsigned a, unsigned b) {
    unsigned d;
    asm("add.rn.bf16x2 %0, %1, %2;" : "=r"(d) : "r"(a), "r"(b));
    return d;
}
__device__ __forceinline__ unsigned hmax2z(unsigned a) {
    unsigned d;
    asm("max.bf16x2 %0, %1, %2;" : "=r"(d) : "r"(a), "r"(0u));
    return d;
}
__device__ __forceinline__ unsigned packcvt(float lo, float hi) {
    unsigned d;
    asm("cvt.rn.bf16x2.f32 %0, %1, %2;" : "=r"(d) : "f"(hi), "f"(lo));
    return d;
}
__device__ __forceinline__ unsigned bcastbf(float x) {
    unsigned d;
    asm("cvt.rn.bf16x2.f32 %0, %1, %1;" : "=r"(d) : "f"(x));
    return d;
}

// ============================================================
// Kernel A: grouped 1x1 conv -> q (+ transposed copy g_qT)
// weights staged in smem transposed [i][o] (coalesced + conflict-free)
// ============================================================
__global__ void k_qproj(const float* __restrict__ x, const float* __restrict__ wq) {
    const int bg = blockIdx.y;
    const int b = bg >> 2, g = bg & 3;
    const int p0 = blockIdx.x * 16;
    const int o = threadIdx.x;

    __shared__ __align__(16) float wqs[CHG * OFFD];   // [i][o]
    __shared__ __align__(16) float xs[CHG * 16];

    const float* wqg = wq + (size_t)g * OFFD * CHG;
    for (int e = o; e < OFFD * CHG; e += 128) {
        int oo = e >> 6, i = e & 63;
        wqs[i * OFFD + oo] = wqg[e];                  // coalesced read
    }
    for (int e = o; e < CHG * 16; e += 128) {
        int i = e >> 4, p = e & 15;
        xs[e] = x[(size_t)(b * DIMC + g * CHG + i) * PQ + p0 + p];
    }
    __syncthreads();

    unsigned long long acc2[8];
#pragma unroll
    for (int q = 0; q < 8; q++) acc2[q] = 0ull;

#pragma unroll 8
    for (int i = 0; i < CHG; i++) {
        float wv0 = wqs[i * OFFD + o];                // conflict-free LDS
        unsigned long long wv = pack2(wv0, wv0);
        const unsigned long long* xr = (const unsigned long long*)(xs + i * 16);
#pragma unroll
        for (int q = 0; q < 8; q++) acc2[q] = ffma2(wv, xr[q], acc2[q]);
    }
    float* qout = g_q + (size_t)(bg * OFFD + o) * PQ + p0;
    float* qtout = g_qT + ((size_t)bg * PQ + p0) * OFFD + o;
#pragma unroll
    for (int q = 0; q < 8; q++) {
        float2 f = unpack2(acc2[q]);
        qout[q * 2 + 0] = f.x;
        qout[q * 2 + 1] = f.y;
        qtout[(q * 2 + 0) * OFFD] = f.x;              // coalesced over o
        qtout[(q * 2 + 1) * OFFD] = f.y;
    }
}

// ============================================================
// Kernel B: offsets -> deformed grid coords
// taps read from g_qT (coalesced over c); dww staged transposed in smem
// ============================================================
__global__ void k_offsets(const float* __restrict__ dww, const float* __restrict__ dwb,
                          const float* __restrict__ pww) {
    const int pos = blockIdx.x;
    const int bg = blockIdx.y;
    const int c = threadIdx.x;
    const int lane = c & 31, wid = c >> 5;

    const int zo = pos >> 6;
    const int yo = (pos >> 3) & 7;
    const int xo = pos & 7;

    __shared__ __align__(16) float dws[64 * OFFD];    // [k][c]
    for (int e = c; e < 64 * OFFD; e += 128) {
        int cc = e >> 6, k = e & 63;
        dws[k * OFFD + cc] = dww[e];                  // coalesced read
    }
    __syncthreads();

    const float* qT = g_qT + (size_t)bg * PQ * OFFD + c;
    float acc = 0.f;
#pragma unroll
    for (int kz = 0; kz < 4; kz++) {
        int z = 2 * zo - 1 + kz;
        if (z < 0 || z >= FF) continue;
#pragma unroll
        for (int ky = 0; ky < 4; ky++) {
            int y = 2 * yo - 1 + ky;
            if (y < 0 || y >= HH) continue;
#pragma unroll
            for (int kx = 0; kx < 4; kx++) {
                int xx = 2 * xo - 1 + kx;
                if (xx < 0 || xx >= WW) continue;
                int p = (z * HH + y) * WW + xx;
                acc = fmaf(qT[(size_t)p * OFFD],      // coalesced over c
                           dws[((kz * 4 + ky) * 4 + kx) * OFFD + c], acc);
            }
        }
    }
    float v = acc + dwb[c];
    float act = 0.5f * v * (1.f + erff(v * 0.70710678118654752f));

    __shared__ float acts[OFFD];
    __shared__ float sred[3];
    acts[c] = act;
    __syncthreads();

    if (wid < 3) {
        float s = 0.f;
#pragma unroll
        for (int q = 0; q < 4; q++) {
            int cc = lane + q * 32;
            s = fmaf(acts[cc], pww[wid * OFFD + cc], s);
        }
#pragma unroll
        for (int off = 16; off; off >>= 1) s += __shfl_xor_sync(0xffffffffu, s, off);
        if (lane == 0) sred[wid] = s;
    }
    __syncthreads();

    if (c == 0) {
        float of = tanhf(sred[0]) * 2.0f;
        float oh = tanhf(sred[1]) * 2.0f;
        float ow = tanhf(sred[2]) * 2.0f;
        float gf = 2.0f * ((float)zo + of) / 1.0f - 1.0f;
        float gh = 2.0f * ((float)yo + oh) / 7.0f - 1.0f;
        float gw = 2.0f * ((float)xo + ow) / 7.0f - 1.0f;
        float* gp = g_grid + (size_t)(bg * PJ + pos) * 3;
        gp[0] = gf; gp[1] = gh; gp[2] = gw;
    }
}

// ============================================================
// Kernel C: trilinear grid-sample + k/v projections
// 16 j per block; wk/wv staged transposed in smem once per block
// ============================================================
__global__ __launch_bounds__(256)
void k_sample_kv(const float* __restrict__ x, const float* __restrict__ wk,
                 const float* __restrict__ wv) {
    const int bg = blockIdx.x;
    const int jt = blockIdx.y;            // 0..7, tile of 16 j
    const int b = bg >> 2, g = bg & 3;
    const int tid = threadIdx.x;

    __shared__ __align__(16) float wks[CHG * OFFD];   // [i][o]
    __shared__ __align__(16) float wvs[CHG * OFFD];
    __shared__ __align__(16) float kvsS[16 * CHG];    // [jl][i]

    const float* wkg = wk + (size_t)g * OFFD * CHG;
    const float* wvg = wv + (size_t)g * OFFD * CHG;
    for (int e = tid; e < OFFD * CHG; e += 256) {
        int o = e >> 6, i = e & 63;
        wks[i * OFFD + o] = wkg[e];
        wvs[i * OFFD + o] = wvg[e];
    }

    // sampling: 4 passes x (4 j x 64 channels)
#pragma unroll
    for (int pass = 0; pass < 4; pass++) {
        int jl = pass * 4 + (tid >> 6);
        int ch = tid & 63;
        int j = jt * 16 + jl;
        const float* gp = g_grid + (size_t)(bg * PJ + j) * 3;
        float g0 = gp[0], g1 = gp[1], g2 = gp[2];
        float ix = ((g0 + 1.f) * (float)WW - 1.f) * 0.5f;
        float iy = ((g1 + 1.f) * (float)HH - 1.f) * 0.5f;
        float iz = ((g2 + 1.f) * (float)FF - 1.f) * 0.5f;
        float fx0 = floorf(ix), fy0 = floorf(iy), fz0 = floorf(iz);
        float tx = ix - fx0, ty = iy - fy0, tz = iz - fz0;
        int x0 = (int)fx0, y0 = (int)fy0, z0 = (int)fz0;

        const float* xp = x + (size_t)(b * DIMC + g * CHG + ch) * PQ;
        float acc = 0.f;
#pragma unroll
        for (int dz = 0; dz < 2; dz++)
#pragma unroll
            for (int dy = 0; dy < 2; dy++)
#pragma unroll
                for (int dx = 0; dx < 2; dx++) {
                    int xc = x0 + dx, yc = y0 + dy, zc = z0 + dz;
                    float wgt = (dx ? tx : 1.f - tx) * (dy ? ty : 1.f - ty) *
                                (dz ? tz : 1.f - tz);
                    bool valid = (xc >= 0) & (xc < WW) & (yc >= 0) & (yc < HH) &
                                 (zc >= 0) & (zc < FF);
                    int xi = min(max(xc, 0), WW - 1);
                    int yi = min(max(yc, 0), HH - 1);
                    int zi = min(max(zc, 0), FF - 1);
                    float val = xp[(zi * HH + yi) * WW + xi];
                    acc += valid ? val * wgt : 0.f;
                }
        kvsS[jl * CHG + ch] = acc;
    }
    __syncthreads();

    // projection: thread = (o, k-or-v); 16 j accumulated in registers
    const int o = tid & 127;
    const int sel = tid >> 7;
    const float* ws = sel ? wvs : wks;
    float* gout = sel ? g_v : g_k;

    float acc[16];
#pragma unroll
    for (int jl = 0; jl < 16; jl++) acc[jl] = 0.f;
#pragma unroll 8
    for (int i = 0; i < CHG; i++) {
        float wv0 = ws[i * OFFD + o];                 // conflict-free LDS
#pragma unroll
        for (int jl = 0; jl < 16; jl++)
            acc[jl] = fmaf(wv0, kvsS[jl * CHG + i], acc[jl]);   // broadcast LDS
    }
    float* orow = gout + (size_t)(bg * OFFD + o) * PJ + jt * 16;
#pragma unroll
    for (int jl = 0; jl < 16; jl++) orow[jl] = acc[jl];
}

// ============================================================
// Kernel D v6 (unchanged): bf16x2 A-gen + dual back-to-back MMA
// ============================================================
__global__ __launch_bounds__(256, 2)
void k_attn(const float* __restrict__ cw0, const float* __restrict__ cb0,
            const float* __restrict__ cw1, const float* __restrict__ cb1,
            const float* __restrict__ cw2, const float* __restrict__ cb2) {
    __shared__ __align__(16) __nv_bfloat16 w1h[CPB * KP];
    __shared__ __align__(16) float ts[IT * 3 * PJ];
    __shared__ __align__(16) float qs[OFFD * IT];
    __shared__ __align__(16) float attns[IT * 2 * PJ];
    __shared__ __align__(16) float simS[IT * 2 * PJ];
    __shared__ __align__(16) uint4 w0p[32];
    __shared__ float w2s[CPB * 2], b1s[CPB];
    __shared__ float sumP[IT * 2 * 8];

    const int bg = blockIdx.y;
    const int b = bg >> 2, g = bg & 3;
    const int i0 = blockIdx.x * IT;
    const int tid = threadIdx.x;
    const int lane = tid & 31, w = tid >> 5;

    for (int e = tid; e < CPB * CPB; e += 256) {
        int k = e >> 6, n = e & 63;
        w1h[n * KP + k] = __float2bfloat16_rn(cw1[e]);
    }
    if (tid < 32) {
        int c = tid * 2;
        uint4 wp;
        wp.x = packcvt(cw0[c], cw0[c + 1]);
        wp.y = packcvt(cw0[64 + c], cw0[64 + c + 1]);
        wp.z = packcvt(cw0[128 + c], cw0[128 + c + 1]);
        wp.w = packcvt(cb0[c], cb0[c + 1]);
        w0p[tid] = wp;
    }
    if (tid >= 64 && tid < 192) w2s[tid - 64] = cw2[tid - 64];
    if (tid >= 192) b1s[tid - 192] = cb1[tid - 192];
    {
        int o = tid >> 1, half = (tid & 1) * 4;
        float4 qv = *(const float4*)(g_q + (size_t)(bg * OFFD + o) * PQ + i0 + half);
        qs[o * IT + half + 0] = qv.x * 0.125f;
        qs[o * IT + half + 1] = qv.y * 0.125f;
        qs[o * IT + half + 2] = qv.z * 0.125f;
        qs[o * IT + half + 3] = qv.w * 0.125f;
    }
    for (int e = tid; e < IT * 3 * PJ; e += 256) {
        int q = e / 384, rem = e - q * 384;
        int d = rem >> 7, j = rem & 127;
        int i = i0 + q;
        float gq;
        if (d == 0) gq = 2.0f * (float)(i >> 8) / 3.0f - 1.0f;
        else if (d == 1) gq = 2.0f * (float)((i >> 4) & 15) / 15.0f - 1.0f;
        else gq = 2.0f * (float)(i & 15) / 15.0f - 1.0f;
        float gj = g_grid[(size_t)(bg * PJ + j) * 3 + d];
        float p = gq - gj;
        ts[e] = copysignf(log1pf(fabsf(p)), p);
    }
    __syncthreads();

    const int r = w * 16 + (lane >> 2);
    const int q2 = lane & 3;
    const int kq = q2 * 2;
    const int nl = lane >> 2;

    unsigned bfr[8][4][2];
#pragma unroll
    for (int nf = 0; nf < 8; nf++) {
        int nrow = nf * 8 + nl;
#pragma unroll
        for (int kt = 0; kt < 4; kt++) {
            bfr[nf][kt][0] = *(const unsigned*)&w1h[nrow * KP + kt * 16 + kq];
            bfr[nf][kt][1] = *(const unsigned*)&w1h[nrow * KP + kt * 16 + kq + 8];
        }
    }
    unsigned bw2[4][2], b1p[4][2];
#pragma unroll
    for (int kt2 = 0; kt2 < 4; kt2++) {
        int k0 = kt2 * 16 + kq;
        bw2[kt2][0] = (nl < 2) ? packcvt(w2s[k0 * 2 + nl], w2s[(k0 + 1) * 2 + nl]) : 0u;
        bw2[kt2][1] = (nl < 2) ? packcvt(w2s[(k0 + 8) * 2 + nl], w2s[(k0 + 9) * 2 + nl]) : 0u;
        b1p[kt2][0] = packcvt(b1s[k0], b1s[k0 + 1]);
        b1p[kt2][1] = packcvt(b1s[k0 + 8], b1s[k0 + 9]);
    }

    {
        const int jj = tid & 127, eh = tid >> 7;
        unsigned long long sim2[4] = {0ull, 0ull, 0ull, 0ull};
        const float* kb = g_k + (size_t)bg * OFFD * PJ + (size_t)eh * 64 * PJ + jj;
#pragma unroll 4
        for (int o = 0; o < 64; o++) {
            float kv = kb[o * PJ];
            unsigned long long kvp = pack2(kv, kv);
            const unsigned long long* qp =
                (const unsigned long long*)(qs + (eh * 64 + o) * IT);
            sim2[0] = ffma2(qp[0], kvp, sim2[0]);
            sim2[1] = ffma2(qp[1], kvp, sim2[1]);
            sim2[2] = ffma2(qp[2], kvp, sim2[2]);
            sim2[3] = ffma2(qp[3], kvp, sim2[3]);
        }
#pragma unroll
        for (int h2 = 0; h2 < 4; h2++) {
            float2 f = unpack2(sim2[h2]);
            simS[((2 * h2 + 0) * 2 + eh) * PJ + jj] = f.x;
            simS[((2 * h2 + 1) * 2 + eh) * PJ + jj] = f.y;
        }
    }
    __syncthreads();

    for (int t = 0; t < IT; t++) {
        const float* tq = ts + t * 3 * PJ;
        unsigned tp0[3], tp1[3];
#pragma unroll
        for (int d = 0; d < 3; d++) {
            tp0[d] = bcastbf(tq[d * PJ + r]);
            tp1[d] = bcastbf(tq[d * PJ + r + 8]);
        }

        unsigned ah[16];
#pragma unroll
        for (int kt = 0; kt < 4; kt++) {
#pragma unroll
            for (int cp = 0; cp < 2; cp++) {
                uint4 W = w0p[kt * 8 + q2 + cp * 4];
                ah[kt * 4 + cp * 2 + 0] =
                    hmax2z(hfma2(tp0[0], W.x, hfma2(tp0[1], W.y, hfma2(tp0[2], W.z, W.w))));
                ah[kt * 4 + cp * 2 + 1] =
                    hmax2z(hfma2(tp1[0], W.x, hfma2(tp1[1], W.y, hfma2(tp1[2], W.z, W.w))));
            }
        }

        float acc2[4] = {0.f, 0.f, 0.f, 0.f};
#pragma unroll
        for (int kt2 = 0; kt2 < 4; kt2++) {
            float accA[4] = {0.f, 0.f, 0.f, 0.f};
            float accB[4] = {0.f, 0.f, 0.f, 0.f};
#pragma unroll
            for (int kt = 0; kt < 4; kt++) {
                mma16816(accA, &ah[kt * 4], bfr[2 * kt2][kt]);
                mma16816(accB, &ah[kt * 4], bfr[2 * kt2 + 1][kt]);
            }
            unsigned a2[4];
            a2[0] = hmax2z(hadd2(packcvt(accA[0], accA[1]), b1p[kt2][0]));
            a2[1] = hmax2z(hadd2(packcvt(accA[2], accA[3]), b1p[kt2][0]));
            a2[2] = hmax2z(hadd2(packcvt(accB[0], accB[1]), b1p[kt2][1]));
            a2[3] = hmax2z(hadd2(packcvt(accB[2], accB[3]), b1p[kt2][1]));
            mma16816(acc2, a2, bw2[kt2]);
        }

        float e00 = __expf(simS[(t * 2 + 0) * PJ + r] + acc2[0]);
        float e01 = __expf(simS[(t * 2 + 1) * PJ + r] + acc2[1]);
        float e10 = __expf(simS[(t * 2 + 0) * PJ + r + 8] + acc2[2]);
        float e11 = __expf(simS[(t * 2 + 1) * PJ + r + 8] + acc2[3]);
        if (q2 == 0) {
            attns[(t * 2 + 0) * PJ + r] = e00;
            attns[(t * 2 + 1) * PJ + r] = e01;
            attns[(t * 2 + 0) * PJ + r + 8] = e10;
            attns[(t * 2 + 1) * PJ + r + 8] = e11;
        }
        float s0 = e00 + e10, s1 = e01 + e11;
#pragma unroll
        for (int off = 4; off <= 16; off <<= 1) {
            s0 += __shfl_xor_sync(0xffffffffu, s0, off);
            s1 += __shfl_xor_sync(0xffffffffu, s1, off);
        }
        if (lane == 0) {
            sumP[(t * 2 + 0) * 8 + w] = s0;
            sumP[(t * 2 + 1) * 8 + w] = s1;
        }
    }
    __syncthreads();

    {
        const int o = tid & 127, qh = tid >> 7, e = o >> 6;
        const ulonglong2* vrow = (const ulonglong2*)(g_v + (size_t)(bg * OFFD + o) * PJ);
        for (int t = qh * 4; t < qh * 4 + 4; t++) {
            const float* sp = sumP + (t * 2 + e) * 8;
            float S = ((sp[0] + sp[1]) + (sp[2] + sp[3])) +
                      ((sp[4] + sp[5]) + (sp[6] + sp[7]));
            const ulonglong2* arow = (const ulonglong2*)(attns + (t * 2 + e) * PJ);
            unsigned long long accA = 0ull, accB = 0ull;
#pragma unroll
            for (int q = 0; q < 32; q++) {
                ulonglong2 av = arow[q];
                ulonglong2 vv = vrow[q];
                accA = ffma2(av.x, vv.x, accA);
                accB = ffma2(av.y, vv.y, accB);
            }
            float2 fa = unpack2(accA), fb = unpack2(accB);
            g_att[(size_t)(b * INNER + g * OFFD + o) * PQ + i0 + t] =
                (fa.x + fa.y + fb.x + fb.y) / S;
        }
    }
}

// ============================================================
// Kernel E: output projection (f32x2 packed inner product)
// ============================================================
__global__ void k_oproj(const float* __restrict__ wo, const float* __restrict__ bo,
                        float* __restrict__ out) {
    const int p0 = blockIdx.x * 64;
    const int o0 = blockIdx.y * 64;
    const int b = blockIdx.z;
    const int tid = threadIdx.x;
    const int tx = tid & 15, ty = tid >> 4;

    __shared__ __align__(16) float As[16 * 64];
    __shared__ __align__(16) float Bs[16 * 64];

    unsigned long long acc2[4][2];
#pragma unroll
    for (int a = 0; a < 4; a++) { acc2[a][0] = 0ull; acc2[a][1] = 0ull; }

    for (int k0 = 0; k0 < INNER; k0 += 16) {
        {
            int m = tid >> 2, kqq = (tid & 3) * 4;
            float4 wv = *(const float4*)(wo + (size_t)(o0 + m) * INNER + k0 + kqq);
            As[(kqq + 0) * 64 + m] = wv.x;
            As[(kqq + 1) * 64 + m] = wv.y;
            As[(kqq + 2) * 64 + m] = wv.z;
            As[(kqq + 3) * 64 + m] = wv.w;
            int k = tid >> 4, pq = (tid & 15) * 4;
            float4 bv = *(const float4*)(g_att + (size_t)(b * INNER + k0 + k) * PQ + p0 + pq);
            *(float4*)(Bs + k * 64 + pq) = bv;
        }
        __syncthreads();
#pragma unroll
        for (int k = 0; k < 16; k++) {
            float4 am = *(const float4*)(As + k * 64 + ty * 4);
            const unsigned long long* bn =
                (const unsigned long long*)(Bs + k * 64 + tx * 4);
            unsigned long long b0 = bn[0], b1 = bn[1];
            unsigned long long a0 = pack2(am.x, am.x);
            unsigned long long a1 = pack2(am.y, am.y);
            unsigned long long a2 = pack2(am.z, am.z);
            unsigned long long a3 = pack2(am.w, am.w);
            acc2[0][0] = ffma2(a0, b0, acc2[0][0]); acc2[0][1] = ffma2(a0, b1, acc2[0][1]);
            acc2[1][0] = ffma2(a1, b0, acc2[1][0]); acc2[1][1] = ffma2(a1, b1, acc2[1][1]);
            acc2[2][0] = ffma2(a2, b0, acc2[2][0]); acc2[2][1] = ffma2(a2, b1, acc2[2][1]);
            acc2[3][0] = ffma2(a3, b0, acc2[3][0]); acc2[3][1] = ffma2(a3, b1, acc2[3][1]);
        }
        __syncthreads();
    }
#pragma unroll
    for (int a = 0; a < 4; a++) {
        float bias = bo[o0 + ty * 4 + a];
        float2 c0 = unpack2(acc2[a][0]);
        float2 c1 = unpack2(acc2[a][1]);
        float* op = out + (size_t)(b * DIMC + o0 + ty * 4 + a) * PQ + p0 + tx * 4;
        op[0] = c0.x + bias;
        op[1] = c0.y + bias;
        op[2] = c1.x + bias;
        op[3] = c1.y + bias;
    }
}

// ============================================================
extern "C" void kernel_launch(void* const* d_in, const int* in_sizes, int n_in,
                              void* d_out, int out_size) {
    const float* x    = (const float*)d_in[0];
    const float* wq   = (const float*)d_in[1];
    const float* wk   = (const float*)d_in[2];
    const float* wv   = (const float*)d_in[3];
    const float* dww  = (const float*)d_in[4];
    const float* dwb  = (const float*)d_in[5];
    const float* pww  = (const float*)d_in[6];
    const float* cw0  = (const float*)d_in[7];
    const float* cb0  = (const float*)d_in[8];
    const float* cw1  = (const float*)d_in[9];
    const float* cb1  = (const float*)d_in[10];
    const float* cw2  = (const float*)d_in[11];
    const float* cb2  = (const float*)d_in[12];
    const float* wo   = (const float*)d_in[13];
    const float* bo   = (const float*)d_in[14];
    float* out = (float*)d_out;
    (void)cb2; // per-head constant bias cancels in softmax

    k_qproj<<<dim3(PQ / 16, NBG), 128>>>(x, wq);
    k_offsets<<<dim3(PJ, NBG), 128>>>(dww, dwb, pww);
    k_sample_kv<<<dim3(NBG, PJ / 16), 256>>>(x, wk, wv);
    k_attn<<<dim3(PQ / IT, NBG), 256>>>(cw0, cb0, cw1, cb1, cw2, cb2);
    k_oproj<<<dim3(PQ / 64, DIMC / 64, BB), 256>>>(wo, bo, out);
}